// round 7
// baseline (speedup 1.0000x reference)
#include <cuda_runtime.h>
#include <cuda_fp16.h>
#include <cstdint>

// ---------------------------------------------------------------------------
// LoRARowParallelLinear, mma.sync fp16 m16n8k16 (compute_103-safe).
//  kernel1 (merged):
//    blocks [0,128):   gemm_lora — u = mask*scal*(x @ lora_A^T), x and lora_A
//                      staged as raw fp32 via 8B cp.async in frag-slot layout,
//                      converted in-loop; u written as fp32 frag slots (g_uf).
//    blocks [128,576): conv W -> fp16 B-frag (g_wh); build Bcat fp16 (g_bcat).
//  kernel2: main GEMM — y = x@W^T (K=4096) + u@Bcat^T (K-ext 128) + bias.
//    A-side: raw fp32 x staged via 8B cp.async into frag slots, cvt in-loop.
//    B-side: fp16 frags (g_wh / g_bcat) via 16B cp.async.
// ---------------------------------------------------------------------------

#define DEVINL static __device__ __forceinline__

namespace {
constexpr int TOK = 8192, DIN = 4096, DOUT = 4096;
constexpr int KB16 = DIN / 16;        // 256 k16-blocks
constexpr int NTI  = KB16 + 8;        // 264 main iterations (incl. K-ext)
}

// scratch (allocation-free __device__ globals)
__device__ __align__(128) uint32_t g_wh  [(DOUT / 8) * KB16 * 64];  // 33.5 MB fp16 B-frag
__device__ __align__(128) uint32_t g_bcat[(DOUT / 8) * 8 * 64];     // 1 MB fp16 B-frag
__device__ __align__(128) float    g_uf  [(TOK / 16) * 8 * 128 * 2];// 4 MB fp32 A-frag slots

DEVINL uint32_t h2pack(float lo, float hi) {
    __half2 h = __float22half2_rn(make_float2(lo, hi));
    return *reinterpret_cast<uint32_t*>(&h);
}

DEVINL void mma_f16(float& d0, float& d1, float& d2, float& d3,
                    uint32_t a0, uint32_t a1, uint32_t a2, uint32_t a3,
                    uint32_t b0, uint32_t b1)
{
    asm volatile(
        "mma.sync.aligned.m16n8k16.row.col.f32.f16.f16.f32 "
        "{%0,%1,%2,%3},{%4,%5,%6,%7},{%8,%9},{%0,%1,%2,%3};"
        : "+f"(d0), "+f"(d1), "+f"(d2), "+f"(d3)
        : "r"(a0), "r"(a1), "r"(a2), "r"(a3), "r"(b0), "r"(b1));
}

DEVINL void cpa16(uint32_t smem_dst, const void* gsrc) {
    asm volatile("cp.async.ca.shared.global [%0], [%1], 16;" :: "r"(smem_dst), "l"(gsrc));
}
DEVINL void cpa8(uint32_t smem_dst, const void* gsrc) {
    asm volatile("cp.async.ca.shared.global [%0], [%1], 8;" :: "r"(smem_dst), "l"(gsrc));
}
DEVINL void cpcommit() { asm volatile("cp.async.commit_group;"); }
template <int N> DEVINL void cpwait() { asm volatile("cp.async.wait_group %0;" :: "n"(N)); }
DEVINL uint32_t s2u(const void* p) {
    uint32_t a;
    asm("{ .reg .u64 t; cvta.to.shared.u64 t, %1; cvt.u32.u64 %0, t; }" : "=r"(a) : "l"(p));
    return a;
}

// ---------------------------------------------------------------------------
// kernel1: merged lora-GEMM (blocks < 128) + W conversion (blocks >= 128)
// ---------------------------------------------------------------------------
__global__ void __launch_bounds__(128, 3) setup_lora_kernel(
    const float* __restrict__ x, const float* __restrict__ la,
    const float* __restrict__ w, const float* __restrict__ lb,
    const int* __restrict__ t2s, const float* __restrict__ scal)
{
    const int tid = threadIdx.x, lane = tid & 31, warp = tid >> 5;

    if (blockIdx.x >= 128) {
        // ---------------- conv W -> g_wh (fp16 B-frag) + bcat ----------------
        __shared__ float cst[4][8 * 36];
        float* s = cst[warp];
        const int gwarp = (blockIdx.x - 128) * 4 + warp;
        const int nwarp = 448 * 4;
        const int r = lane >> 2, coff = (lane & 3) * 8;
        const int g = lane >> 2, k0 = (lane & 3) * 2;

        for (int sb = gwarp; sb < 512 * 128; sb += nwarp) {
            const int nt = sb >> 7, kt2 = sb & 127;
            const float* base = w + (size_t)(nt * 8) * DIN + kt2 * 32;
            #pragma unroll
            for (int q = 0; q < 2; q++)
                *reinterpret_cast<float4*>(s + r * 36 + coff + q * 4) =
                    *reinterpret_cast<const float4*>(base + (size_t)r * DIN + coff + q * 4);
            __syncwarp();
            #pragma unroll
            for (int kb = 0; kb < 2; kb++) {
                const int K = kb * 16;
                uint2 v;
                v.x = h2pack(s[g * 36 + K + k0],     s[g * 36 + K + k0 + 1]);
                v.y = h2pack(s[g * 36 + K + k0 + 8], s[g * 36 + K + k0 + 9]);
                *reinterpret_cast<uint2*>(
                    g_wh + ((size_t)nt * KB16 + kt2 * 2 + kb) * 64 + lane * 2) = v;
            }
            __syncwarp();
        }

        // lora_B [8][DOUT][16] -> g_bcat fp16 B-frag: Bcat[n][s*16+r]=lB[s][n][r]
        const int nth = 448 * 128;
        const int gt  = (blockIdx.x - 128) * 128 + tid;
        for (int i = gt; i < DOUT * 64; i += nth) {
            const int n = i >> 6, p = i & 63;
            const int kc = p * 2;
            const int sl = kc >> 4, rr = kc & 15;
            const float f0 = lb[(size_t)sl * DOUT * 16 + n * 16 + rr];
            const float f1 = lb[(size_t)sl * DOUT * 16 + n * 16 + rr + 1];
            const int nt = n >> 3, gg = n & 7;
            const int kbb  = kc >> 4;
            const int lpos = gg * 4 + ((kc & 7) >> 1);
            const int word = lpos * 2 + ((kc >> 3) & 1);
            g_bcat[((size_t)nt * 8 + kbb) * 64 + word] = h2pack(f0, f1);
        }
        return;
    }

    // ---------------- lora GEMM: u = mask*scal*(x @ lora_A^T) ----------------
    // CTA 64x128, 4 warps (warp 32x64), BK=16, 4 stages (A 4KB fp32 + B 8KB fp32)
    constexpr int STAGE_B = 4096 + 8192;
    extern __shared__ char smem[];
    const uint32_t sbase = s2u(smem);
    const int wm = warp >> 1, wn = warp & 1;
    const int bm = blockIdx.x;

    // per-thread copy descriptors: A 4 copies, B 8 copies
    int aoff[4], adw[4];
    #pragma unroll
    for (int j = 0; j < 4; j++) {
        const int idx = tid * 4 + j;
        const int mt = idx >> 7, sl = idx & 127, l = sl >> 2, q = sl & 3;
        const int gg = l >> 2, c = l & 3;
        const int row = bm * 64 + mt * 16 + gg + (q & 1) * 8;
        aoff[j] = row * DIN + c * 2 + (q >> 1) * 8;
        adw[j]  = (mt * 128 + sl) * 8;
    }
    int boff[8], bdw[8];
    #pragma unroll
    for (int j = 0; j < 8; j++) {
        const int idx = tid * 8 + j;
        const int nt = idx >> 6, s6 = idx & 63, l = s6 >> 1, q = s6 & 1;
        const int gg = l >> 2, c = l & 3;
        boff[j] = (nt * 8 + gg) * DIN + c * 2 + q * 8;
        bdw[j]  = 4096 + (nt * 64 + s6) * 8;
    }

    float acc[2][8][4];
    #pragma unroll
    for (int i = 0; i < 2; i++)
        #pragma unroll
        for (int j = 0; j < 8; j++)
            #pragma unroll
            for (int k = 0; k < 4; k++) acc[i][j][k] = 0.f;

    auto load_stage = [&](int f, int buf) {
        const uint32_t st = sbase + buf * STAGE_B;
        const int kc = f * 16;
        #pragma unroll
        for (int j = 0; j < 4; j++) cpa8(st + adw[j], x + aoff[j] + kc);
        #pragma unroll
        for (int j = 0; j < 8; j++) cpa8(st + bdw[j], la + boff[j] + kc);
    };

    load_stage(0, 0); cpcommit();
    load_stage(1, 1); cpcommit();
    load_stage(2, 2); cpcommit();

    for (int ci = 0; ci < KB16; ci++) {
        cpwait<2>();
        __syncthreads();
        if (ci + 3 < KB16) load_stage(ci + 3, (ci + 3) & 3);
        cpcommit();

        const float* sAf = reinterpret_cast<const float*>(smem + (ci & 3) * STAGE_B);
        const float* sBf = sAf + 1024;

        uint32_t a[2][4];
        #pragma unroll
        for (int i = 0; i < 2; i++) {
            const float4* ap = reinterpret_cast<const float4*>(
                sAf + ((wm * 2 + i) * 128 + lane * 4) * 2);
            const float4 v0 = ap[0], v1 = ap[1];
            a[i][0] = h2pack(v0.x, v0.y); a[i][1] = h2pack(v0.z, v0.w);
            a[i][2] = h2pack(v1.x, v1.y); a[i][3] = h2pack(v1.z, v1.w);
        }
        uint32_t b[8][2];
        #pragma unroll
        for (int j = 0; j < 8; j++) {
            const float4 v = *reinterpret_cast<const float4*>(
                sBf + ((wn * 8 + j) * 64 + lane * 2) * 2);
            b[j][0] = h2pack(v.x, v.y); b[j][1] = h2pack(v.z, v.w);
        }
        #pragma unroll
        for (int i = 0; i < 2; i++)
            #pragma unroll
            for (int j = 0; j < 8; j++)
                mma_f16(acc[i][j][0], acc[i][j][1], acc[i][j][2], acc[i][j][3],
                        a[i][0], a[i][1], a[i][2], a[i][3], b[j][0], b[j][1]);
    }

    // epilogue: mask*scale -> g_uf fp32 frag slots
    #pragma unroll
    for (int i = 0; i < 2; i++) {
        const int mrow0 = bm * 64 + wm * 32 + i * 16 + (lane >> 2);
        const int slot0 = t2s[mrow0];
        const int slot1 = t2s[mrow0 + 8];
        const float sc0 = scal[slot0];
        const float sc1 = scal[slot1];
        const int mt = bm * 4 + wm * 2 + i;
        #pragma unroll
        for (int j = 0; j < 8; j += 2) {
            const int kbg = wn * 4 + (j >> 1);
            const int n0 = wn * 64 + j * 8 + (lane & 3) * 2;
            const int n1 = n0 + 8;
            const float m00 = ((n0 >> 4) == slot0) ? sc0 : 0.f;
            const float m01 = ((n0 >> 4) == slot1) ? sc1 : 0.f;
            const float m10 = ((n1 >> 4) == slot0) ? sc0 : 0.f;
            const float m11 = ((n1 >> 4) == slot1) ? sc1 : 0.f;
            float* base = g_uf + (((size_t)mt * 8 + kbg) * 128 + lane * 4) * 2;
            float4 v0, v1;
            v0.x = acc[i][j][0] * m00;     v0.y = acc[i][j][1] * m00;
            v0.z = acc[i][j][2] * m01;     v0.w = acc[i][j][3] * m01;
            v1.x = acc[i][j + 1][0] * m10; v1.y = acc[i][j + 1][1] * m10;
            v1.z = acc[i][j + 1][2] * m11; v1.w = acc[i][j + 1][3] * m11;
            *reinterpret_cast<float4*>(base)     = v0;
            *reinterpret_cast<float4*>(base + 4) = v1;
        }
    }
}

// ---------------------------------------------------------------------------
// kernel2: main GEMM — CTA 128x128, 4 warps (warp 64x64), BK=16, 6 stages.
// A-side fp32 x inline (8B cp.async frag slots + in-loop cvt), B-side fp16.
// ---------------------------------------------------------------------------
__global__ void __launch_bounds__(128, 2) gemm_main(
    const float* __restrict__ x, float* __restrict__ C,
    const float* __restrict__ bias)
{
    constexpr int STAGE_B = 8192 + 4096;   // A 8KB fp32 + B 4KB fp16
    extern __shared__ char smem[];
    const uint32_t sbase = s2u(smem);
    const int tid = threadIdx.x, lane = tid & 31, warp = tid >> 5;
    const int wm = warp >> 1, wn = warp & 1;
    const int bm = blockIdx.y, bn = blockIdx.x;

    // per-thread copy descriptors: A 8 copies (8B), B 2 copies (16B)
    int aoff[8], adw[8], auo[8];
    #pragma unroll
    for (int j = 0; j < 8; j++) {
        const int idx = tid * 8 + j;
        const int mt = idx >> 7, sl = idx & 127, l = sl >> 2, q = sl & 3;
        const int gg = l >> 2, c = l & 3;
        const int row = bm * 128 + mt * 16 + gg + (q & 1) * 8;
        aoff[j] = row * DIN + c * 2 + (q >> 1) * 8;
        adw[j]  = (mt * 128 + sl) * 8;
        auo[j]  = (bm * 8 + mt) * 2048 + sl * 2;
    }
    int bwo[2], bco[2], bdw[2];
    #pragma unroll
    for (int j = 0; j < 2; j++) {
        const int idx = tid * 2 + j;
        const int nt = idx >> 4, c16 = idx & 15;
        bwo[j] = ((bn * 16 + nt) * KB16) * 64 + c16 * 4;
        bco[j] = ((bn * 16 + nt) * 8) * 64 + c16 * 4;
        bdw[j] = 8192 + (nt * 64 + c16 * 4) * 4;
    }

    float acc[4][8][4];
    #pragma unroll
    for (int i = 0; i < 4; i++)
        #pragma unroll
        for (int j = 0; j < 8; j++)
            #pragma unroll
            for (int k = 0; k < 4; k++) acc[i][j][k] = 0.f;

    auto load_stage = [&](int f, int buf) {
        const uint32_t st = sbase + buf * STAGE_B;
        if (f < KB16) {
            const int kc = f * 16;
            #pragma unroll
            for (int j = 0; j < 8; j++) cpa8(st + adw[j], x + aoff[j] + kc);
            #pragma unroll
            for (int j = 0; j < 2; j++) cpa16(st + bdw[j], g_wh + bwo[j] + f * 64);
        } else {
            const int fe = f - KB16;
            #pragma unroll
            for (int j = 0; j < 8; j++) cpa8(st + adw[j], g_uf + auo[j] + fe * 256);
            #pragma unroll
            for (int j = 0; j < 2; j++) cpa16(st + bdw[j], g_bcat + bco[j] + fe * 64);
        }
    };

    #pragma unroll
    for (int s = 0; s < 5; s++) { load_stage(s, s); cpcommit(); }

    for (int ci = 0; ci < NTI; ci++) {
        cpwait<4>();
        __syncthreads();
        if (ci + 5 < NTI) load_stage(ci + 5, (ci + 5) % 6);
        cpcommit();

        const float* sAf = reinterpret_cast<const float*>(smem + (ci % 6) * STAGE_B);
        const uint32_t* sBw = reinterpret_cast<const uint32_t*>(
            smem + (ci % 6) * STAGE_B + 8192);

        uint32_t a[4][4];
        #pragma unroll
        for (int i = 0; i < 4; i++) {
            const float4* ap = reinterpret_cast<const float4*>(
                sAf + ((wm * 4 + i) * 128 + lane * 4) * 2);
            const float4 v0 = ap[0], v1 = ap[1];
            a[i][0] = h2pack(v0.x, v0.y); a[i][1] = h2pack(v0.z, v0.w);
            a[i][2] = h2pack(v1.x, v1.y); a[i][3] = h2pack(v1.z, v1.w);
        }
        uint32_t b[8][2];
        #pragma unroll
        for (int j = 0; j < 8; j++) {
            const uint2 v = *reinterpret_cast<const uint2*>(
                sBw + (wn * 8 + j) * 64 + lane * 2);
            b[j][0] = v.x; b[j][1] = v.y;
        }
        #pragma unroll
        for (int i = 0; i < 4; i++)
            #pragma unroll
            for (int j = 0; j < 8; j++)
                mma_f16(acc[i][j][0], acc[i][j][1], acc[i][j][2], acc[i][j][3],
                        a[i][0], a[i][1], a[i][2], a[i][3], b[j][0], b[j][1]);
    }

    // epilogue: + bias -> y
    const int nb = bn * 128 + wn * 64;
    #pragma unroll
    for (int i = 0; i < 4; i++) {
        #pragma unroll
        for (int h = 0; h < 2; h++) {
            const int m = bm * 128 + wm * 64 + i * 16 + h * 8 + (lane >> 2);
            float* crow = C + (size_t)m * DOUT + nb + (lane & 3) * 2;
            #pragma unroll
            for (int j = 0; j < 8; j++) {
                const float2 bv = *reinterpret_cast<const float2*>(
                    bias + nb + j * 8 + (lane & 3) * 2);
                float2 v;
                v.x = acc[i][j][h * 2 + 0] + bv.x;
                v.y = acc[i][j][h * 2 + 1] + bv.y;
                *reinterpret_cast<float2*>(crow + j * 8) = v;
            }
        }
    }
}

// ---------------------------------------------------------------------------
extern "C" void kernel_launch(void* const* d_in, const int* in_sizes, int n_in,
                              void* d_out, int out_size)
{
    const float* x    = (const float*)d_in[0];
    const int*   t2s  = (const int*)  d_in[1];
    const float* w    = (const float*)d_in[2];
    const float* bias = (const float*)d_in[3];
    const float* lA   = (const float*)d_in[4];
    const float* lB   = (const float*)d_in[5];
    const float* scal = (const float*)d_in[6];
    float*       y    = (float*)d_out;

    constexpr int SMEM0 = 4 * (4096 + 8192);  // 48 KB (lora part)
    constexpr int SMEM1 = 6 * (8192 + 4096);  // 72 KB (main)

    cudaFuncSetAttribute(setup_lora_kernel, cudaFuncAttributeMaxDynamicSharedMemorySize, SMEM0);
    cudaFuncSetAttribute(gemm_main, cudaFuncAttributeMaxDynamicSharedMemorySize, SMEM1);

    // kernel1: lora GEMM (blocks 0..127) in parallel with W conversion (128..575)
    setup_lora_kernel<<<576, 128, SMEM0>>>(x, lA, w, lB, t2s, scal);

    // kernel2: main GEMM
    gemm_main<<<dim3(DOUT / 128, TOK / 128), 128, SMEM1>>>(x, y, bias);
}

// round 8
// speedup vs baseline: 2.0584x; 2.0584x over previous
#include <cuda_runtime.h>
#include <cuda_fp16.h>
#include <cstdint>

// ---------------------------------------------------------------------------
// LoRARowParallelLinear, mma.sync fp16 m16n8k16 (compute_103-safe).
//  kernel1 (merged setup):
//    blocks [0,128):   lora GEMM u = mask*scal*(x @ lora_A^T) with inline
//                      fp32->fp16 conversion; side-writes x fp16 A-frags to
//                      g_xh; u written as fp16 A-frags (g_uh).
//    blocks [128,576): W -> fp16 B-frag (g_wh); Bcat fp16 (g_bcat).
//  kernel2: main GEMM y = x@W^T (K=4096) + u@Bcat^T (K-ext 128) + bias.
//    All-fp16 staging (16B cp.async), 6 stages, barrier every 2 iters.
// ---------------------------------------------------------------------------

#define DEVINL static __device__ __forceinline__

namespace {
constexpr int TOK = 8192, DIN = 4096, DOUT = 4096;
constexpr int KB16 = DIN / 16;        // 256 k16-blocks
constexpr int NTI  = 132;             // 128 main BK32 iters + 4 K-ext iters
}

// scratch (allocation-free __device__ globals)
__device__ __align__(128) uint32_t g_xh  [(TOK / 16) * KB16 * 128];  // 67 MB fp16 A-frag
__device__ __align__(128) uint32_t g_wh  [(DOUT / 8) * KB16 * 64];   // 33.5 MB fp16 B-frag
__device__ __align__(128) uint32_t g_bcat[(DOUT / 8) * 8 * 64];      // 1 MB fp16 B-frag
__device__ __align__(128) uint32_t g_uh  [(TOK / 16) * 8 * 128];     // 2 MB fp16 A-frag

DEVINL uint32_t h2pack(float lo, float hi) {
    __half2 h = __float22half2_rn(make_float2(lo, hi));
    return *reinterpret_cast<uint32_t*>(&h);
}

DEVINL void mma_f16(float& d0, float& d1, float& d2, float& d3,
                    uint32_t a0, uint32_t a1, uint32_t a2, uint32_t a3,
                    uint32_t b0, uint32_t b1)
{
    asm volatile(
        "mma.sync.aligned.m16n8k16.row.col.f32.f16.f16.f32 "
        "{%0,%1,%2,%3},{%4,%5,%6,%7},{%8,%9},{%0,%1,%2,%3};"
        : "+f"(d0), "+f"(d1), "+f"(d2), "+f"(d3)
        : "r"(a0), "r"(a1), "r"(a2), "r"(a3), "r"(b0), "r"(b1));
}

DEVINL void cpa16(uint32_t smem_dst, const void* gsrc) {
    asm volatile("cp.async.ca.shared.global [%0], [%1], 16;" :: "r"(smem_dst), "l"(gsrc));
}
DEVINL void cpa8(uint32_t smem_dst, const void* gsrc) {
    asm volatile("cp.async.ca.shared.global [%0], [%1], 8;" :: "r"(smem_dst), "l"(gsrc));
}
DEVINL void cpcommit() { asm volatile("cp.async.commit_group;"); }
template <int N> DEVINL void cpwait() { asm volatile("cp.async.wait_group %0;" :: "n"(N)); }
DEVINL uint32_t s2u(const void* p) {
    uint32_t a;
    asm("{ .reg .u64 t; cvta.to.shared.u64 t, %1; cvt.u32.u64 %0, t; }" : "=r"(a) : "l"(p));
    return a;
}

// ---------------------------------------------------------------------------
// kernel1: merged setup.
// ---------------------------------------------------------------------------
__global__ void __launch_bounds__(128) setup_kernel(
    const float* __restrict__ x, const float* __restrict__ la,
    const float* __restrict__ w, const float* __restrict__ lb,
    const int* __restrict__ t2s, const float* __restrict__ scal)
{
    const int tid = threadIdx.x, lane = tid & 31, warp = tid >> 5;

    if (blockIdx.x >= 128) {
        // ---------------- conv W -> g_wh (fp16 B-frag) + bcat ----------------
        __shared__ float cst[4][8 * 36];
        float* s = cst[warp];
        const int gwarp = (blockIdx.x - 128) * 4 + warp;
        const int nwarp = 448 * 4;
        const int r = lane >> 2, coff = (lane & 3) * 8;
        const int g = lane >> 2, k0 = (lane & 3) * 2;

        for (int sb = gwarp; sb < 512 * 128; sb += nwarp) {
            const int nt = sb >> 7, kt2 = sb & 127;
            const float* base = w + (size_t)(nt * 8) * DIN + kt2 * 32;
            #pragma unroll
            for (int q = 0; q < 2; q++)
                *reinterpret_cast<float4*>(s + r * 36 + coff + q * 4) =
                    *reinterpret_cast<const float4*>(base + (size_t)r * DIN + coff + q * 4);
            __syncwarp();
            #pragma unroll
            for (int kb = 0; kb < 2; kb++) {
                const int K = kb * 16;
                uint2 v;
                v.x = h2pack(s[g * 36 + K + k0],     s[g * 36 + K + k0 + 1]);
                v.y = h2pack(s[g * 36 + K + k0 + 8], s[g * 36 + K + k0 + 9]);
                *reinterpret_cast<uint2*>(
                    g_wh + ((size_t)nt * KB16 + kt2 * 2 + kb) * 64 + lane * 2) = v;
            }
            __syncwarp();
        }

        // lora_B [8][DOUT][16] -> g_bcat fp16 B-frag: Bcat[n][s*16+r]=lB[s][n][r]
        const int nth = 448 * 128;
        const int gt  = (blockIdx.x - 128) * 128 + tid;
        for (int i = gt; i < DOUT * 64; i += nth) {
            const int n = i >> 6, p = i & 63;
            const int kc = p * 2;
            const int sl = kc >> 4, rr = kc & 15;
            const float f0 = lb[(size_t)sl * DOUT * 16 + n * 16 + rr];
            const float f1 = lb[(size_t)sl * DOUT * 16 + n * 16 + rr + 1];
            const int nt = n >> 3, gg = n & 7;
            const int kbb  = kc >> 4;
            const int lpos = gg * 4 + ((kc & 7) >> 1);
            const int word = lpos * 2 + ((kc >> 3) & 1);
            g_bcat[((size_t)nt * 8 + kbb) * 64 + word] = h2pack(f0, f1);
        }
        return;
    }

    // ---- lora GEMM: u = mask*scal*(x @ lora_A^T); side-write g_xh ----
    // CTA 64x128, 4 warps (warp 32x64), BK=16, 4 stages (A 4KB + B 8KB fp32)
    constexpr int STAGE_B = 4096 + 8192;
    extern __shared__ char smem[];
    const uint32_t sbase = s2u(smem);
    const int wm = warp >> 1, wn = warp & 1;
    const int bm = blockIdx.x;

    int aoff[4], adw[4];
    #pragma unroll
    for (int j = 0; j < 4; j++) {
        const int idx = tid * 4 + j;
        const int mt = idx >> 7, sl = idx & 127, l = sl >> 2, q = sl & 3;
        const int gg = l >> 2, c = l & 3;
        const int row = bm * 64 + mt * 16 + gg + (q & 1) * 8;
        aoff[j] = row * DIN + c * 2 + (q >> 1) * 8;
        adw[j]  = (mt * 128 + sl) * 8;
    }
    int boff[8], bdw[8];
    #pragma unroll
    for (int j = 0; j < 8; j++) {
        const int idx = tid * 8 + j;
        const int nt = idx >> 6, s6 = idx & 63, l = s6 >> 1, q = s6 & 1;
        const int gg = l >> 2, c = l & 3;
        boff[j] = (nt * 8 + gg) * DIN + c * 2 + q * 8;
        bdw[j]  = 4096 + (nt * 64 + s6) * 8;
    }

    float acc[2][8][4];
    #pragma unroll
    for (int i = 0; i < 2; i++)
        #pragma unroll
        for (int j = 0; j < 8; j++)
            #pragma unroll
            for (int k = 0; k < 4; k++) acc[i][j][k] = 0.f;

    auto load_stage = [&](int f, int buf) {
        const uint32_t st = sbase + buf * STAGE_B;
        const int kc = f * 16;
        #pragma unroll
        for (int j = 0; j < 4; j++) cpa8(st + adw[j], x + aoff[j] + kc);
        #pragma unroll
        for (int j = 0; j < 8; j++) cpa8(st + bdw[j], la + boff[j] + kc);
    };

    load_stage(0, 0); cpcommit();
    load_stage(1, 1); cpcommit();
    load_stage(2, 2); cpcommit();

    for (int ci = 0; ci < KB16; ci++) {
        cpwait<2>();
        __syncthreads();
        if (ci + 3 < KB16) load_stage(ci + 3, (ci + 3) & 3);
        cpcommit();

        const float* sAf = reinterpret_cast<const float*>(smem + (ci & 3) * STAGE_B);
        const float* sBf = sAf + 1024;

        uint32_t a[2][4];
        #pragma unroll
        for (int i = 0; i < 2; i++) {
            const float4* ap = reinterpret_cast<const float4*>(
                sAf + ((wm * 2 + i) * 128 + lane * 4) * 2);
            const float4 v0 = ap[0], v1 = ap[1];
            a[i][0] = h2pack(v0.x, v0.y); a[i][1] = h2pack(v0.z, v0.w);
            a[i][2] = h2pack(v1.x, v1.y); a[i][3] = h2pack(v1.z, v1.w);
        }
        // side-write x fp16 A-frags (wn==0 warps): exactly g_xh layout
        if (wn == 0) {
            #pragma unroll
            for (int i = 0; i < 2; i++) {
                uint4 v = make_uint4(a[i][0], a[i][1], a[i][2], a[i][3]);
                *reinterpret_cast<uint4*>(
                    g_xh + ((size_t)(bm * 4 + wm * 2 + i) * KB16 + ci) * 128 + lane * 4) = v;
            }
        }
        uint32_t b[8][2];
        #pragma unroll
        for (int j = 0; j < 8; j++) {
            const float4 v = *reinterpret_cast<const float4*>(
                sBf + ((wn * 8 + j) * 64 + lane * 2) * 2);
            b[j][0] = h2pack(v.x, v.y); b[j][1] = h2pack(v.z, v.w);
        }
        #pragma unroll
        for (int i = 0; i < 2; i++)
            #pragma unroll
            for (int j = 0; j < 8; j++)
                mma_f16(acc[i][j][0], acc[i][j][1], acc[i][j][2], acc[i][j][3],
                        a[i][0], a[i][1], a[i][2], a[i][3], b[j][0], b[j][1]);
    }

    // epilogue: mask*scale -> g_uh fp16 A-frag blocks
    #pragma unroll
    for (int i = 0; i < 2; i++) {
        const int mrow0 = bm * 64 + wm * 32 + i * 16 + (lane >> 2);
        const int slot0 = t2s[mrow0];
        const int slot1 = t2s[mrow0 + 8];
        const float sc0 = scal[slot0];
        const float sc1 = scal[slot1];
        const int mt = bm * 4 + wm * 2 + i;
        #pragma unroll
        for (int j = 0; j < 8; j += 2) {
            const int kbg = wn * 4 + (j >> 1);
            const int n0 = wn * 64 + j * 8 + (lane & 3) * 2;
            const int n1 = n0 + 8;
            const float m00 = ((n0 >> 4) == slot0) ? sc0 : 0.f;
            const float m01 = ((n0 >> 4) == slot1) ? sc1 : 0.f;
            const float m10 = ((n1 >> 4) == slot0) ? sc0 : 0.f;
            const float m11 = ((n1 >> 4) == slot1) ? sc1 : 0.f;
            uint4 v;
            v.x = h2pack(acc[i][j][0] * m00,     acc[i][j][1] * m00);
            v.y = h2pack(acc[i][j][2] * m01,     acc[i][j][3] * m01);
            v.z = h2pack(acc[i][j + 1][0] * m10, acc[i][j + 1][1] * m10);
            v.w = h2pack(acc[i][j + 1][2] * m11, acc[i][j + 1][3] * m11);
            *reinterpret_cast<uint4*>(g_uh + ((size_t)mt * 8 + kbg) * 128 + lane * 4) = v;
        }
    }
}

// ---------------------------------------------------------------------------
// kernel2: main GEMM — CTA 128x128, 4 warps (warp 64x64), BK=32, 6 stages,
// barrier every 2 iterations (fill distance 3, cpwait<2>).
// ---------------------------------------------------------------------------
__global__ void __launch_bounds__(128, 2) gemm_main(
    float* __restrict__ C, const float* __restrict__ bias)
{
    constexpr int A_ST = 2048, B_ST = 2048, STW = A_ST + B_ST;  // words/stage
    extern __shared__ uint32_t sm[];
    const int tid = threadIdx.x, lane = tid & 31, warp = tid >> 5;
    const int wm = warp >> 1, wn = warp & 1;
    const int bm = blockIdx.y, bn = blockIdx.x;

    float acc[4][8][4];
    #pragma unroll
    for (int i = 0; i < 4; i++)
        #pragma unroll
        for (int j = 0; j < 8; j++)
            #pragma unroll
            for (int k = 0; k < 4; k++) acc[i][j][k] = 0.f;

    auto load_stage = [&](int f, int buf) {
        uint32_t* sA = sm + buf * STW;
        uint32_t* sB = sA + A_ST;
        #pragma unroll
        for (int q = tid; q < 512; q += 128) {
            const int mt = q >> 6, kb = (q >> 5) & 1, c = q & 31;
            const uint32_t* src = (f < 128)
                ? g_xh + ((size_t)(bm * 8 + mt) * KB16 + f * 2 + kb) * 128 + c * 4
                : g_uh + ((size_t)(bm * 8 + mt) * 8 + (f - 128) * 2 + kb) * 128 + c * 4;
            cpa16(s2u(sA + (mt * 2 + kb) * 128 + c * 4), src);
        }
        #pragma unroll
        for (int q = tid; q < 512; q += 128) {
            const int nt = q >> 5, kb = (q >> 4) & 1, c = q & 15;
            const uint32_t* src = (f < 128)
                ? g_wh   + ((size_t)(bn * 16 + nt) * KB16 + f * 2 + kb) * 64 + c * 4
                : g_bcat + ((size_t)(bn * 16 + nt) * 8 + (f - 128) * 2 + kb) * 64 + c * 4;
            cpa16(s2u(sB + (nt * 2 + kb) * 64 + c * 4), src);
        }
    };

    auto compute = [&](int ci) {
        const uint32_t* sA = sm + (ci % 6) * STW;
        const uint32_t* sB = sA + A_ST;
        const uint32_t* aw = sA + (wm * 4) * 2 * 128 + lane * 4;
        const uint32_t* bw = sB + (wn * 8) * 2 * 64 + lane * 2;
        #pragma unroll
        for (int kb = 0; kb < 2; kb++) {
            uint4 a[4];
            #pragma unroll
            for (int i = 0; i < 4; i++)
                a[i] = *reinterpret_cast<const uint4*>(aw + (i * 2 + kb) * 128);
            uint2 b[8];
            #pragma unroll
            for (int j = 0; j < 8; j++)
                b[j] = *reinterpret_cast<const uint2*>(bw + (j * 2 + kb) * 64);
            #pragma unroll
            for (int i = 0; i < 4; i++)
                #pragma unroll
                for (int j = 0; j < 8; j++)
                    mma_f16(acc[i][j][0], acc[i][j][1], acc[i][j][2], acc[i][j][3],
                            a[i].x, a[i].y, a[i].z, a[i].w, b[j].x, b[j].y);
        }
    };

    load_stage(0, 0); cpcommit();
    load_stage(1, 1); cpcommit();
    load_stage(2, 2); cpcommit();

    for (int ci = 0; ci < NTI; ci += 2) {
        // even iteration: fill, wait, barrier, compute
        if (ci + 3 < NTI) load_stage(ci + 3, (ci + 3) % 6);
        cpcommit();
        cpwait<2>();
        __syncthreads();
        compute(ci);
        // odd iteration: fill + compute, no barrier
        if (ci + 4 < NTI) load_stage(ci + 4, (ci + 4) % 6);
        cpcommit();
        compute(ci + 1);
    }

    // epilogue: + bias -> y
    const int nb = bn * 128 + wn * 64;
    #pragma unroll
    for (int i = 0; i < 4; i++) {
        #pragma unroll
        for (int h = 0; h < 2; h++) {
            const int m = bm * 128 + wm * 64 + i * 16 + h * 8 + (lane >> 2);
            float* crow = C + (size_t)m * DOUT + nb + (lane & 3) * 2;
            #pragma unroll
            for (int j = 0; j < 8; j++) {
                const float2 bv = *reinterpret_cast<const float2*>(
                    bias + nb + j * 8 + (lane & 3) * 2);
                float2 v;
                v.x = acc[i][j][h * 2 + 0] + bv.x;
                v.y = acc[i][j][h * 2 + 1] + bv.y;
                *reinterpret_cast<float2*>(crow + j * 8) = v;
            }
        }
    }
}

// ---------------------------------------------------------------------------
extern "C" void kernel_launch(void* const* d_in, const int* in_sizes, int n_in,
                              void* d_out, int out_size)
{
    const float* x    = (const float*)d_in[0];
    const int*   t2s  = (const int*)  d_in[1];
    const float* w    = (const float*)d_in[2];
    const float* bias = (const float*)d_in[3];
    const float* lA   = (const float*)d_in[4];
    const float* lB   = (const float*)d_in[5];
    const float* scal = (const float*)d_in[6];
    float*       y    = (float*)d_out;

    constexpr int SMEM0 = 4 * (4096 + 8192);   // 48 KB (lora blocks)
    constexpr int SMEM1 = 6 * (2048 + 2048) * 4;  // 96 KB (main, 6 stages)

    cudaFuncSetAttribute(setup_kernel, cudaFuncAttributeMaxDynamicSharedMemorySize, SMEM0);
    cudaFuncSetAttribute(gemm_main,    cudaFuncAttributeMaxDynamicSharedMemorySize, SMEM1);

    // kernel1: lora GEMM + x conversion (blocks 0..127) || W conv + bcat (128..575)
    setup_kernel<<<576, 128, SMEM0>>>(x, lA, w, lB, t2s, scal);

    // kernel2: main GEMM
    gemm_main<<<dim3(DOUT / 128, TOK / 128), 128, SMEM1>>>(y, bias);
}

// round 9
// speedup vs baseline: 2.7364x; 1.3294x over previous
#include <cuda_runtime.h>
#include <cuda_fp16.h>
#include <cstdint>

// ---------------------------------------------------------------------------
// LoRARowParallelLinear, mma.sync fp16 m16n8k16 (compute_103-safe).
//  conv_x: x -> fp16 A-frags (g_xh), lora_A -> fp16 B-frags (g_lah).
//  setup2: blocks [0,128)  lora GEMM u = mask*scal*(x @ lora_A^T) -> g_uh
//          blocks [128,576) W -> fp16 B-frags (g_wh) + Bcat (g_bcat)
//  main:   y = x@W^T (K=4096) + u@Bcat^T (K-ext 128, same accum) + bias.
//          CTA 128x128, 256 thr (8 warps, warp 32x64), 6 stages, occ 2,
//          barrier every 2 iterations. 4 warps/SMSP to keep HMMA pipe fed.
// ---------------------------------------------------------------------------

#define DEVINL static __device__ __forceinline__

namespace {
constexpr int TOK = 8192, DIN = 4096, DOUT = 4096;
constexpr int KB16 = DIN / 16;   // 256 k16-blocks
constexpr int NTI  = 132;        // 128 main BK32 iters + 4 K-ext iters
}

// scratch (allocation-free __device__ globals)
__device__ __align__(128) uint32_t g_xh  [(TOK / 16) * KB16 * 128];  // 67 MB
__device__ __align__(128) uint32_t g_wh  [(DOUT / 8) * KB16 * 64];   // 33.5 MB
__device__ __align__(128) uint32_t g_lah [16 * KB16 * 64];           // 1 MB
__device__ __align__(128) uint32_t g_bcat[(DOUT / 8) * 8 * 64];      // 1 MB
__device__ __align__(128) uint32_t g_uh  [(TOK / 16) * 8 * 128];     // 2 MB

DEVINL uint32_t h2pack(float lo, float hi) {
    __half2 h = __float22half2_rn(make_float2(lo, hi));
    return *reinterpret_cast<uint32_t*>(&h);
}

DEVINL void mma_f16(float& d0, float& d1, float& d2, float& d3,
                    uint32_t a0, uint32_t a1, uint32_t a2, uint32_t a3,
                    uint32_t b0, uint32_t b1)
{
    asm volatile(
        "mma.sync.aligned.m16n8k16.row.col.f32.f16.f16.f32 "
        "{%0,%1,%2,%3},{%4,%5,%6,%7},{%8,%9},{%0,%1,%2,%3};"
        : "+f"(d0), "+f"(d1), "+f"(d2), "+f"(d3)
        : "r"(a0), "r"(a1), "r"(a2), "r"(a3), "r"(b0), "r"(b1));
}

DEVINL void cpa16(const uint32_t* smem_dst, const void* gsrc) {
    uint32_t s = (uint32_t)__cvta_generic_to_shared(smem_dst);
    asm volatile("cp.async.ca.shared.global [%0], [%1], 16;" :: "r"(s), "l"(gsrc));
}
DEVINL void cpcommit() { asm volatile("cp.async.commit_group;"); }
template <int N> DEVINL void cpwait() { asm volatile("cp.async.wait_group %0;" :: "n"(N)); }

// ---------------------------------------------------------------------------
// conv_x: x -> g_xh (A-frag fp16), lora_A -> g_lah (B-frag fp16). smem-staged.
// ---------------------------------------------------------------------------
__global__ void __launch_bounds__(256) conv_x_kernel(
    const float* __restrict__ x, const float* __restrict__ la)
{
    __shared__ float st[8][16 * 36];
    const int tid  = threadIdx.x;
    const int lane = tid & 31, warp = tid >> 5;
    const int gwarp = blockIdx.x * 8 + warp;
    const int nwarp = gridDim.x * 8;
    float* s = st[warp];
    const int g  = lane >> 2;
    const int k0 = (lane & 3) * 2;

    // x -> g_xh. Superblock = 16 rows x 32 cols (2 k16-blocks).
    {
        const int r = lane >> 1, coff = (lane & 1) * 16;
        for (int sb = gwarp; sb < 512 * 128; sb += nwarp) {
            const int mt = sb >> 7, kt2 = sb & 127;
            const float* base = x + (size_t)(mt * 16) * DIN + kt2 * 32;
            #pragma unroll
            for (int q = 0; q < 4; q++)
                *reinterpret_cast<float4*>(s + r * 36 + coff + q * 4) =
                    *reinterpret_cast<const float4*>(base + (size_t)r * DIN + coff + q * 4);
            __syncwarp();
            #pragma unroll
            for (int kb = 0; kb < 2; kb++) {
                const int K = kb * 16;
                uint4 v;
                v.x = h2pack(s[g * 36 + K + k0],           s[g * 36 + K + k0 + 1]);
                v.y = h2pack(s[(g + 8) * 36 + K + k0],     s[(g + 8) * 36 + K + k0 + 1]);
                v.z = h2pack(s[g * 36 + K + k0 + 8],       s[g * 36 + K + k0 + 9]);
                v.w = h2pack(s[(g + 8) * 36 + K + k0 + 8], s[(g + 8) * 36 + K + k0 + 9]);
                *reinterpret_cast<uint4*>(
                    g_xh + ((size_t)mt * KB16 + kt2 * 2 + kb) * 128 + lane * 4) = v;
            }
            __syncwarp();
        }
    }

    // lora_A -> g_lah (B-frag, 16 n-tiles). Superblock = 8 rows x 32 cols.
    {
        const int r = lane >> 2, coff = (lane & 3) * 8;
        for (int sb = gwarp; sb < 16 * 128; sb += nwarp) {
            const int nt = sb >> 7, kt2 = sb & 127;
            const float* base = la + (size_t)(nt * 8) * DIN + kt2 * 32;
            #pragma unroll
            for (int q = 0; q < 2; q++)
                *reinterpret_cast<float4*>(s + r * 36 + coff + q * 4) =
                    *reinterpret_cast<const float4*>(base + (size_t)r * DIN + coff + q * 4);
            __syncwarp();
            #pragma unroll
            for (int kb = 0; kb < 2; kb++) {
                const int K = kb * 16;
                uint2 v;
                v.x = h2pack(s[g * 36 + K + k0],     s[g * 36 + K + k0 + 1]);
                v.y = h2pack(s[g * 36 + K + k0 + 8], s[g * 36 + K + k0 + 9]);
                *reinterpret_cast<uint2*>(
                    g_lah + ((size_t)nt * KB16 + kt2 * 2 + kb) * 64 + lane * 2) = v;
            }
            __syncwarp();
        }
    }
}

// ---------------------------------------------------------------------------
// setup2: lora GEMM (blocks < 128) || W conversion + Bcat (blocks >= 128).
// lora: CTA 64x128, 4 warps (warp 32x64), BK=32, 4 stages (48KB), reads
// g_xh/g_lah, writes g_uh fp16 A-frags.  (R6-proven code.)
// ---------------------------------------------------------------------------
__global__ void __launch_bounds__(128) setup2_kernel(
    const float* __restrict__ w, const float* __restrict__ lb,
    const int* __restrict__ t2s, const float* __restrict__ scal)
{
    const int tid = threadIdx.x, lane = tid & 31, warp = tid >> 5;

    if (blockIdx.x >= 128) {
        // -------- conv W -> g_wh (fp16 B-frag) + bcat --------
        __shared__ float cst[4][8 * 36];
        float* s = cst[warp];
        const int gwarp = (blockIdx.x - 128) * 4 + warp;
        const int nwarp = 448 * 4;
        const int r = lane >> 2, coff = (lane & 3) * 8;
        const int g = lane >> 2, k0 = (lane & 3) * 2;

        for (int sb = gwarp; sb < 512 * 128; sb += nwarp) {
            const int nt = sb >> 7, kt2 = sb & 127;
            const float* base = w + (size_t)(nt * 8) * DIN + kt2 * 32;
            #pragma unroll
            for (int q = 0; q < 2; q++)
                *reinterpret_cast<float4*>(s + r * 36 + coff + q * 4) =
                    *reinterpret_cast<const float4*>(base + (size_t)r * DIN + coff + q * 4);
            __syncwarp();
            #pragma unroll
            for (int kb = 0; kb < 2; kb++) {
                const int K = kb * 16;
                uint2 v;
                v.x = h2pack(s[g * 36 + K + k0],     s[g * 36 + K + k0 + 1]);
                v.y = h2pack(s[g * 36 + K + k0 + 8], s[g * 36 + K + k0 + 9]);
                *reinterpret_cast<uint2*>(
                    g_wh + ((size_t)nt * KB16 + kt2 * 2 + kb) * 64 + lane * 2) = v;
            }
            __syncwarp();
        }

        // lora_B [8][DOUT][16] -> g_bcat: Bcat[n][s*16+r] = lB[s][n][r]
        const int nth = 448 * 128;
        const int gt  = (blockIdx.x - 128) * 128 + tid;
        for (int i = gt; i < DOUT * 64; i += nth) {
            const int n = i >> 6, p = i & 63;
            const int kc = p * 2;
            const int sl = kc >> 4, rr = kc & 15;
            const float f0 = lb[(size_t)sl * DOUT * 16 + n * 16 + rr];
            const float f1 = lb[(size_t)sl * DOUT * 16 + n * 16 + rr + 1];
            const int nt = n >> 3, gg = n & 7;
            const int kbb  = kc >> 4;
            const int lpos = gg * 4 + ((kc & 7) >> 1);
            const int word = lpos * 2 + ((kc >> 3) & 1);
            g_bcat[((size_t)nt * 8 + kbb) * 64 + word] = h2pack(f0, f1);
        }
        return;
    }

    // -------- lora GEMM (R6-proven): u = mask*scal*(x @ lora_A^T) --------
    constexpr int A_ST = 1024, B_ST = 2048, STW = A_ST + B_ST;  // words
    extern __shared__ uint32_t sm[];
    const int wm = warp >> 1, wn = warp & 1;
    const int bm = blockIdx.x;

    float acc[2][8][4];
    #pragma unroll
    for (int i = 0; i < 2; i++)
        #pragma unroll
        for (int j = 0; j < 8; j++)
            #pragma unroll
            for (int k = 0; k < 4; k++) acc[i][j][k] = 0.f;

    auto load_stage = [&](int f, int buf) {
        uint32_t* sA = sm + buf * STW;
        uint32_t* sB = sA + A_ST;
        #pragma unroll
        for (int q = tid; q < 256; q += 128) {
            const int mt = q >> 6, kb = (q >> 5) & 1, c = q & 31;
            cpa16(sA + (mt * 2 + kb) * 128 + c * 4,
                  g_xh + ((size_t)(bm * 4 + mt) * KB16 + f * 2 + kb) * 128 + c * 4);
        }
        #pragma unroll
        for (int q = tid; q < 512; q += 128) {
            const int nt = q >> 5, kb = (q >> 4) & 1, c = q & 15;
            cpa16(sB + (nt * 2 + kb) * 64 + c * 4,
                  g_lah + ((size_t)nt * KB16 + f * 2 + kb) * 64 + c * 4);
        }
    };

    load_stage(0, 0); cpcommit();
    load_stage(1, 1); cpcommit();
    load_stage(2, 2); cpcommit();

    for (int ci = 0; ci < 128; ci++) {
        cpwait<2>();
        __syncthreads();
        if (ci + 3 < 128) load_stage(ci + 3, (ci + 3) & 3);
        cpcommit();

        const uint32_t* sA = sm + (ci & 3) * STW;
        const uint32_t* sB = sA + A_ST;
        const uint32_t* aw = sA + (wm * 2) * 2 * 128 + lane * 4;
        const uint32_t* bw = sB + (wn * 8) * 2 * 64 + lane * 2;

        #pragma unroll
        for (int kb = 0; kb < 2; kb++) {
            uint4 a[2];
            a[0] = *reinterpret_cast<const uint4*>(aw + kb * 128);
            a[1] = *reinterpret_cast<const uint4*>(aw + (2 + kb) * 128);
            uint2 b[8];
            #pragma unroll
            for (int j = 0; j < 8; j++)
                b[j] = *reinterpret_cast<const uint2*>(bw + (j * 2 + kb) * 64);
            #pragma unroll
            for (int i = 0; i < 2; i++)
                #pragma unroll
                for (int j = 0; j < 8; j++)
                    mma_f16(acc[i][j][0], acc[i][j][1], acc[i][j][2], acc[i][j][3],
                            a[i].x, a[i].y, a[i].z, a[i].w, b[j].x, b[j].y);
        }
    }

    // epilogue: mask*scale -> g_uh fp16 A-frag blocks
    #pragma unroll
    for (int i = 0; i < 2; i++) {
        const int mrow0 = bm * 64 + wm * 32 + i * 16 + (lane >> 2);
        const int slot0 = t2s[mrow0];
        const int slot1 = t2s[mrow0 + 8];
        const float sc0 = scal[slot0];
        const float sc1 = scal[slot1];
        const int mt = bm * 4 + wm * 2 + i;
        #pragma unroll
        for (int j = 0; j < 8; j += 2) {
            const int kbg = wn * 4 + (j >> 1);
            const int n0 = wn * 64 + j * 8 + (lane & 3) * 2;
            const int n1 = n0 + 8;
            const float m00 = ((n0 >> 4) == slot0) ? sc0 : 0.f;
            const float m01 = ((n0 >> 4) == slot1) ? sc1 : 0.f;
            const float m10 = ((n1 >> 4) == slot0) ? sc0 : 0.f;
            const float m11 = ((n1 >> 4) == slot1) ? sc1 : 0.f;
            uint4 v;
            v.x = h2pack(acc[i][j][0] * m00,     acc[i][j][1] * m00);
            v.y = h2pack(acc[i][j][2] * m01,     acc[i][j][3] * m01);
            v.z = h2pack(acc[i][j + 1][0] * m10, acc[i][j + 1][1] * m10);
            v.w = h2pack(acc[i][j + 1][2] * m11, acc[i][j + 1][3] * m11);
            *reinterpret_cast<uint4*>(g_uh + ((size_t)mt * 8 + kbg) * 128 + lane * 4) = v;
        }
    }
}

// ---------------------------------------------------------------------------
// main GEMM: CTA 128x128, 256 thr (8 warps, warp 32x64), BK=32, 6 stages,
// barrier every 2 iterations. 4 warps/SMSP at occ 2.
// ---------------------------------------------------------------------------
__global__ void __launch_bounds__(256, 2) gemm_main(
    float* __restrict__ C, const float* __restrict__ bias)
{
    constexpr int A_ST = 2048, B_ST = 2048, STW = A_ST + B_ST;  // words/stage
    extern __shared__ uint32_t sm[];
    const int tid = threadIdx.x, lane = tid & 31, warp = tid >> 5;
    const int wm = warp >> 1, wn = warp & 1;   // warp tile 32x64
    const int bm = blockIdx.y, bn = blockIdx.x;

    float acc[2][8][4];
    #pragma unroll
    for (int i = 0; i < 2; i++)
        #pragma unroll
        for (int j = 0; j < 8; j++)
            #pragma unroll
            for (int k = 0; k < 4; k++) acc[i][j][k] = 0.f;

    auto load_stage = [&](int f, int buf) {
        uint32_t* sA = sm + buf * STW;
        uint32_t* sB = sA + A_ST;
        #pragma unroll
        for (int q = tid; q < 512; q += 256) {
            const int mt = q >> 6, kb = (q >> 5) & 1, c = q & 31;
            const uint32_t* src = (f < 128)
                ? g_xh + ((size_t)(bm * 8 + mt) * KB16 + f * 2 + kb) * 128 + c * 4
                : g_uh + ((size_t)(bm * 8 + mt) * 8 + (f - 128) * 2 + kb) * 128 + c * 4;
            cpa16(sA + (mt * 2 + kb) * 128 + c * 4, src);
        }
        #pragma unroll
        for (int q = tid; q < 512; q += 256) {
            const int nt = q >> 5, kb = (q >> 4) & 1, c = q & 15;
            const uint32_t* src = (f < 128)
                ? g_wh   + ((size_t)(bn * 16 + nt) * KB16 + f * 2 + kb) * 64 + c * 4
                : g_bcat + ((size_t)(bn * 16 + nt) * 8 + (f - 128) * 2 + kb) * 64 + c * 4;
            cpa16(sB + (nt * 2 + kb) * 64 + c * 4, src);
        }
    };

    auto compute = [&](int ci) {
        const uint32_t* sA = sm + (ci % 6) * STW;
        const uint32_t* sB = sA + A_ST;
        const uint32_t* aw = sA + (wm * 2) * 2 * 128 + lane * 4;
        const uint32_t* bw = sB + (wn * 8) * 2 * 64 + lane * 2;
        #pragma unroll
        for (int kb = 0; kb < 2; kb++) {
            uint4 a[2];
            a[0] = *reinterpret_cast<const uint4*>(aw + kb * 128);
            a[1] = *reinterpret_cast<const uint4*>(aw + (2 + kb) * 128);
            uint2 b[8];
            #pragma unroll
            for (int j = 0; j < 8; j++)
                b[j] = *reinterpret_cast<const uint2*>(bw + (j * 2 + kb) * 64);
            #pragma unroll
            for (int i = 0; i < 2; i++)
                #pragma unroll
                for (int j = 0; j < 8; j++)
                    mma_f16(acc[i][j][0], acc[i][j][1], acc[i][j][2], acc[i][j][3],
                            a[i].x, a[i].y, a[i].z, a[i].w, b[j].x, b[j].y);
        }
    };

    load_stage(0, 0); cpcommit();
    load_stage(1, 1); cpcommit();
    load_stage(2, 2); cpcommit();

    for (int ci = 0; ci < NTI; ci += 2) {
        if (ci + 3 < NTI) load_stage(ci + 3, (ci + 3) % 6);
        cpcommit();
        cpwait<2>();
        __syncthreads();
        compute(ci);
        if (ci + 4 < NTI) load_stage(ci + 4, (ci + 4) % 6);
        cpcommit();
        compute(ci + 1);
    }

    // epilogue: + bias -> y
    const int nb = bn * 128 + wn * 64;
    #pragma unroll
    for (int i = 0; i < 2; i++) {
        #pragma unroll
        for (int h = 0; h < 2; h++) {
            const int m = bm * 128 + wm * 32 + i * 16 + h * 8 + (lane >> 2);
            float* crow = C + (size_t)m * DOUT + nb + (lane & 3) * 2;
            #pragma unroll
            for (int j = 0; j < 8; j++) {
                const float2 bv = *reinterpret_cast<const float2*>(
                    bias + nb + j * 8 + (lane & 3) * 2);
                float2 v;
                v.x = acc[i][j][h * 2 + 0] + bv.x;
                v.y = acc[i][j][h * 2 + 1] + bv.y;
                *reinterpret_cast<float2*>(crow + j * 8) = v;
            }
        }
    }
}

// ---------------------------------------------------------------------------
extern "C" void kernel_launch(void* const* d_in, const int* in_sizes, int n_in,
                              void* d_out, int out_size)
{
    const float* x    = (const float*)d_in[0];
    const int*   t2s  = (const int*)  d_in[1];
    const float* w    = (const float*)d_in[2];
    const float* bias = (const float*)d_in[3];
    const float* lA   = (const float*)d_in[4];
    const float* lB   = (const float*)d_in[5];
    const float* scal = (const float*)d_in[6];
    float*       y    = (float*)d_out;

    constexpr int SMEM0 = 4 * (1024 + 2048) * 4;  // 48 KB (lora)
    constexpr int SMEM1 = 6 * (2048 + 2048) * 4;  // 96 KB (main)

    cudaFuncSetAttribute(setup2_kernel, cudaFuncAttributeMaxDynamicSharedMemorySize, SMEM0);
    cudaFuncSetAttribute(gemm_main,     cudaFuncAttributeMaxDynamicSharedMemorySize, SMEM1);

    // 1) x + lora_A -> fp16 frags
    conv_x_kernel<<<1184, 256>>>(x, lA);
    // 2) lora GEMM (blocks 0..127) || W conversion + Bcat (blocks 128..575)
    setup2_kernel<<<576, 128, SMEM0>>>(w, lB, t2s, scal);
    // 3) main GEMM
    gemm_main<<<dim3(DOUT / 128, TOK / 128), 256, SMEM1>>>(y, bias);
}

// round 10
// speedup vs baseline: 3.2387x; 1.1836x over previous
#include <cuda_runtime.h>
#include <cuda_fp16.h>
#include <cstdint>

// ---------------------------------------------------------------------------
// LoRARowParallelLinear, mma.sync fp16 m16n8k16 (compute_103-safe).
// Best-measured assembly:
//   conv  (R6): x -> fp16 A-frags, W/lora_A -> fp16 B-frags, Bcat.  (~50us)
//   lora  (R6): u = mask*scal*(x @ lora_A^T) -> g_uh fp16 A-frags.  (~20us)
//   main  (R8): y = x@W^T (K=4096) + u@Bcat^T (K-ext) + bias.       (667us)
//               CTA 128x128, 4 warps (64x64 warp tile), 6 stages, occ 2,
//               barrier every 2 iterations.
// ---------------------------------------------------------------------------

#define DEVINL static __device__ __forceinline__

namespace {
constexpr int TOK = 8192, DIN = 4096, DOUT = 4096;
constexpr int KB16 = DIN / 16;   // 256 k16-blocks
constexpr int NTI  = 132;        // 128 main BK32 iters + 4 K-ext iters
}

// scratch (allocation-free __device__ globals)
__device__ __align__(128) uint32_t g_xh  [(TOK / 16) * KB16 * 128];  // 67 MB
__device__ __align__(128) uint32_t g_wh  [(DOUT / 8) * KB16 * 64];   // 33.5 MB
__device__ __align__(128) uint32_t g_lah [16 * KB16 * 64];           // 1 MB
__device__ __align__(128) uint32_t g_bcat[(DOUT / 8) * 8 * 64];      // 1 MB
__device__ __align__(128) uint32_t g_uh  [(TOK / 16) * 8 * 128];     // 2 MB

DEVINL uint32_t h2pack(float lo, float hi) {
    __half2 h = __float22half2_rn(make_float2(lo, hi));
    return *reinterpret_cast<uint32_t*>(&h);
}

DEVINL void mma_f16(float& d0, float& d1, float& d2, float& d3,
                    uint32_t a0, uint32_t a1, uint32_t a2, uint32_t a3,
                    uint32_t b0, uint32_t b1)
{
    asm volatile(
        "mma.sync.aligned.m16n8k16.row.col.f32.f16.f16.f32 "
        "{%0,%1,%2,%3},{%4,%5,%6,%7},{%8,%9},{%0,%1,%2,%3};"
        : "+f"(d0), "+f"(d1), "+f"(d2), "+f"(d3)
        : "r"(a0), "r"(a1), "r"(a2), "r"(a3), "r"(b0), "r"(b1));
}

DEVINL void cpa16(const uint32_t* smem_dst, const void* gsrc) {
    uint32_t s = (uint32_t)__cvta_generic_to_shared(smem_dst);
    asm volatile("cp.async.ca.shared.global [%0], [%1], 16;" :: "r"(s), "l"(gsrc));
}
DEVINL void cpcommit() { asm volatile("cp.async.commit_group;"); }
template <int N> DEVINL void cpwait() { asm volatile("cp.async.wait_group %0;" :: "n"(N)); }

// ---------------------------------------------------------------------------
// conv (R6): fp32 -> packed fp16 frag-major, staged through smem.
// ---------------------------------------------------------------------------
__global__ void __launch_bounds__(256) conv_kernel(
    const float* __restrict__ x, const float* __restrict__ w,
    const float* __restrict__ la, const float* __restrict__ lb)
{
    __shared__ float st[8][16 * 36];
    const int tid  = threadIdx.x;
    const int lane = tid & 31, warp = tid >> 5;
    const int gwarp = blockIdx.x * 8 + warp;
    const int nwarp = gridDim.x * 8;
    float* s = st[warp];
    const int g  = lane >> 2;
    const int k0 = (lane & 3) * 2;

    // x -> g_xh (A-frag). Superblock = 16 rows x 32 cols (2 k-blocks).
    {
        const int r = lane >> 1, coff = (lane & 1) * 16;
        for (int sb = gwarp; sb < 512 * 128; sb += nwarp) {
            const int mt = sb >> 7, kt2 = sb & 127;
            const float* base = x + (size_t)(mt * 16) * DIN + kt2 * 32;
            #pragma unroll
            for (int q = 0; q < 4; q++)
                *reinterpret_cast<float4*>(s + r * 36 + coff + q * 4) =
                    *reinterpret_cast<const float4*>(base + (size_t)r * DIN + coff + q * 4);
            __syncwarp();
            #pragma unroll
            for (int kb = 0; kb < 2; kb++) {
                const int K = kb * 16;
                uint4 v;
                v.x = h2pack(s[g * 36 + K + k0],           s[g * 36 + K + k0 + 1]);
                v.y = h2pack(s[(g + 8) * 36 + K + k0],     s[(g + 8) * 36 + K + k0 + 1]);
                v.z = h2pack(s[g * 36 + K + k0 + 8],       s[g * 36 + K + k0 + 9]);
                v.w = h2pack(s[(g + 8) * 36 + K + k0 + 8], s[(g + 8) * 36 + K + k0 + 9]);
                *reinterpret_cast<uint4*>(
                    g_xh + ((size_t)mt * KB16 + kt2 * 2 + kb) * 128 + lane * 4) = v;
            }
            __syncwarp();
        }
    }

    // w -> g_wh (B-frag). Superblock = 8 rows x 32 cols (2 k-blocks).
    {
        const int r = lane >> 2, coff = (lane & 3) * 8;
        for (int sb = gwarp; sb < 512 * 128; sb += nwarp) {
            const int nt = sb >> 7, kt2 = sb & 127;
            const float* base = w + (size_t)(nt * 8) * DIN + kt2 * 32;
            #pragma unroll
            for (int q = 0; q < 2; q++)
                *reinterpret_cast<float4*>(s + r * 36 + coff + q * 4) =
                    *reinterpret_cast<const float4*>(base + (size_t)r * DIN + coff + q * 4);
            __syncwarp();
            #pragma unroll
            for (int kb = 0; kb < 2; kb++) {
                const int K = kb * 16;
                uint2 v;
                v.x = h2pack(s[g * 36 + K + k0],     s[g * 36 + K + k0 + 1]);
                v.y = h2pack(s[g * 36 + K + k0 + 8], s[g * 36 + K + k0 + 9]);
                *reinterpret_cast<uint2*>(
                    g_wh + ((size_t)nt * KB16 + kt2 * 2 + kb) * 64 + lane * 2) = v;
            }
            __syncwarp();
        }
    }

    // lora_A -> g_lah (B-frag, 16 n-tiles)
    {
        const int r = lane >> 2, coff = (lane & 3) * 8;
        for (int sb = gwarp; sb < 16 * 128; sb += nwarp) {
            const int nt = sb >> 7, kt2 = sb & 127;
            const float* base = la + (size_t)(nt * 8) * DIN + kt2 * 32;
            #pragma unroll
            for (int q = 0; q < 2; q++)
                *reinterpret_cast<float4*>(s + r * 36 + coff + q * 4) =
                    *reinterpret_cast<const float4*>(base + (size_t)r * DIN + coff + q * 4);
            __syncwarp();
            #pragma unroll
            for (int kb = 0; kb < 2; kb++) {
                const int K = kb * 16;
                uint2 v;
                v.x = h2pack(s[g * 36 + K + k0],     s[g * 36 + K + k0 + 1]);
                v.y = h2pack(s[g * 36 + K + k0 + 8], s[g * 36 + K + k0 + 9]);
                *reinterpret_cast<uint2*>(
                    g_lah + ((size_t)nt * KB16 + kt2 * 2 + kb) * 64 + lane * 2) = v;
            }
            __syncwarp();
        }
    }

    // lora_B [8][DOUT][16] -> g_bcat (B-frag): Bcat[n][s*16+r] = lB[s][n][r]
    const int nth = gridDim.x * blockDim.x;
    const int gt  = blockIdx.x * 256 + tid;
    for (int i = gt; i < DOUT * 64; i += nth) {
        const int n = i >> 6, p = i & 63;
        const int kc = p * 2;
        const int sl = kc >> 4, rr = kc & 15;
        const float f0 = lb[(size_t)sl * DOUT * 16 + n * 16 + rr];
        const float f1 = lb[(size_t)sl * DOUT * 16 + n * 16 + rr + 1];
        const int nt = n >> 3, gg = n & 7;
        const int kbb  = kc >> 4;
        const int lpos = gg * 4 + ((kc & 7) >> 1);
        const int word = lpos * 2 + ((kc >> 3) & 1);
        g_bcat[((size_t)nt * 8 + kbb) * 64 + word] = h2pack(f0, f1);
    }
}

// ---------------------------------------------------------------------------
// lora (R6): u = mask*scal*(x @ lora_A^T) -> g_uh (fp16 A-frag).
// CTA 64x128, 128 thr (4 warps, warp 32x64), BK=32, 4 stages, 48KB.
// ---------------------------------------------------------------------------
__global__ void __launch_bounds__(128, 3) gemm_lora(
    const int* __restrict__ t2s, const float* __restrict__ scal)
{
    constexpr int A_ST = 1024, B_ST = 2048, STW = A_ST + B_ST;  // words
    extern __shared__ uint32_t sm[];
    const int tid = threadIdx.x, lane = tid & 31, warp = tid >> 5;
    const int wm = warp >> 1, wn = warp & 1;
    const int bm = blockIdx.y;

    float acc[2][8][4];
    #pragma unroll
    for (int i = 0; i < 2; i++)
        #pragma unroll
        for (int j = 0; j < 8; j++)
            #pragma unroll
            for (int k = 0; k < 4; k++) acc[i][j][k] = 0.f;

    auto load_stage = [&](int f, int buf) {
        uint32_t* sA = sm + buf * STW;
        uint32_t* sB = sA + A_ST;
        #pragma unroll
        for (int q = tid; q < 256; q += 128) {
            const int mt = q >> 6, kb = (q >> 5) & 1, c = q & 31;
            cpa16(sA + (mt * 2 + kb) * 128 + c * 4,
                  g_xh + ((size_t)(bm * 4 + mt) * KB16 + f * 2 + kb) * 128 + c * 4);
        }
        #pragma unroll
        for (int q = tid; q < 512; q += 128) {
            const int nt = q >> 5, kb = (q >> 4) & 1, c = q & 15;
            cpa16(sB + (nt * 2 + kb) * 64 + c * 4,
                  g_lah + ((size_t)nt * KB16 + f * 2 + kb) * 64 + c * 4);
        }
    };

    load_stage(0, 0); cpcommit();
    load_stage(1, 1); cpcommit();
    load_stage(2, 2); cpcommit();

    for (int ci = 0; ci < 128; ci++) {
        cpwait<2>();
        __syncthreads();
        if (ci + 3 < 128) load_stage(ci + 3, (ci + 3) & 3);
        cpcommit();

        const uint32_t* sA = sm + (ci & 3) * STW;
        const uint32_t* sB = sA + A_ST;
        const uint32_t* aw = sA + (wm * 2) * 2 * 128 + lane * 4;
        const uint32_t* bw = sB + (wn * 8) * 2 * 64 + lane * 2;

        #pragma unroll
        for (int kb = 0; kb < 2; kb++) {
            uint4 a[2];
            a[0] = *reinterpret_cast<const uint4*>(aw + kb * 128);
            a[1] = *reinterpret_cast<const uint4*>(aw + (2 + kb) * 128);
            uint2 b[8];
            #pragma unroll
            for (int j = 0; j < 8; j++)
                b[j] = *reinterpret_cast<const uint2*>(bw + (j * 2 + kb) * 64);
            #pragma unroll
            for (int i = 0; i < 2; i++)
                #pragma unroll
                for (int j = 0; j < 8; j++)
                    mma_f16(acc[i][j][0], acc[i][j][1], acc[i][j][2], acc[i][j][3],
                            a[i].x, a[i].y, a[i].z, a[i].w, b[j].x, b[j].y);
        }
    }

    // epilogue: mask*scale -> g_uh fp16 A-frag blocks
    #pragma unroll
    for (int i = 0; i < 2; i++) {
        const int mrow0 = bm * 64 + wm * 32 + i * 16 + (lane >> 2);
        const int slot0 = t2s[mrow0];
        const int slot1 = t2s[mrow0 + 8];
        const float sc0 = scal[slot0];
        const float sc1 = scal[slot1];
        const int mt = bm * 4 + wm * 2 + i;
        #pragma unroll
        for (int j = 0; j < 8; j += 2) {
            const int kbg = wn * 4 + (j >> 1);
            const int n0 = wn * 64 + j * 8 + (lane & 3) * 2;
            const int n1 = n0 + 8;
            const float m00 = ((n0 >> 4) == slot0) ? sc0 : 0.f;
            const float m01 = ((n0 >> 4) == slot1) ? sc1 : 0.f;
            const float m10 = ((n1 >> 4) == slot0) ? sc0 : 0.f;
            const float m11 = ((n1 >> 4) == slot1) ? sc1 : 0.f;
            uint4 v;
            v.x = h2pack(acc[i][j][0] * m00,     acc[i][j][1] * m00);
            v.y = h2pack(acc[i][j][2] * m01,     acc[i][j][3] * m01);
            v.z = h2pack(acc[i][j + 1][0] * m10, acc[i][j + 1][1] * m10);
            v.w = h2pack(acc[i][j + 1][2] * m11, acc[i][j + 1][3] * m11);
            *reinterpret_cast<uint4*>(g_uh + ((size_t)mt * 8 + kbg) * 128 + lane * 4) = v;
        }
    }
}

// ---------------------------------------------------------------------------
// main (R8): CTA 128x128, 128 thr (4 warps, warp 64x64), BK=32, 6 stages,
// occ 2, barrier every 2 iterations.
// ---------------------------------------------------------------------------
__global__ void __launch_bounds__(128, 2) gemm_main(
    float* __restrict__ C, const float* __restrict__ bias)
{
    constexpr int A_ST = 2048, B_ST = 2048, STW = A_ST + B_ST;  // words/stage
    extern __shared__ uint32_t sm[];
    const int tid = threadIdx.x, lane = tid & 31, warp = tid >> 5;
    const int wm = warp >> 1, wn = warp & 1;
    const int bm = blockIdx.y, bn = blockIdx.x;

    float acc[4][8][4];
    #pragma unroll
    for (int i = 0; i < 4; i++)
        #pragma unroll
        for (int j = 0; j < 8; j++)
            #pragma unroll
            for (int k = 0; k < 4; k++) acc[i][j][k] = 0.f;

    auto load_stage = [&](int f, int buf) {
        uint32_t* sA = sm + buf * STW;
        uint32_t* sB = sA + A_ST;
        #pragma unroll
        for (int q = tid; q < 512; q += 128) {
            const int mt = q >> 6, kb = (q >> 5) & 1, c = q & 31;
            const uint32_t* src = (f < 128)
                ? g_xh + ((size_t)(bm * 8 + mt) * KB16 + f * 2 + kb) * 128 + c * 4
                : g_uh + ((size_t)(bm * 8 + mt) * 8 + (f - 128) * 2 + kb) * 128 + c * 4;
            cpa16(sA + (mt * 2 + kb) * 128 + c * 4, src);
        }
        #pragma unroll
        for (int q = tid; q < 512; q += 128) {
            const int nt = q >> 5, kb = (q >> 4) & 1, c = q & 15;
            const uint32_t* src = (f < 128)
                ? g_wh   + ((size_t)(bn * 16 + nt) * KB16 + f * 2 + kb) * 64 + c * 4
                : g_bcat + ((size_t)(bn * 16 + nt) * 8 + (f - 128) * 2 + kb) * 64 + c * 4;
            cpa16(sB + (nt * 2 + kb) * 64 + c * 4, src);
        }
    };

    auto compute = [&](int ci) {
        const uint32_t* sA = sm + (ci % 6) * STW;
        const uint32_t* sB = sA + A_ST;
        const uint32_t* aw = sA + (wm * 4) * 2 * 128 + lane * 4;
        const uint32_t* bw = sB + (wn * 8) * 2 * 64 + lane * 2;
        #pragma unroll
        for (int kb = 0; kb < 2; kb++) {
            uint4 a[4];
            #pragma unroll
            for (int i = 0; i < 4; i++)
                a[i] = *reinterpret_cast<const uint4*>(aw + (i * 2 + kb) * 128);
            uint2 b[8];
            #pragma unroll
            for (int j = 0; j < 8; j++)
                b[j] = *reinterpret_cast<const uint2*>(bw + (j * 2 + kb) * 64);
            #pragma unroll
            for (int i = 0; i < 4; i++)
                #pragma unroll
                for (int j = 0; j < 8; j++)
                    mma_f16(acc[i][j][0], acc[i][j][1], acc[i][j][2], acc[i][j][3],
                            a[i].x, a[i].y, a[i].z, a[i].w, b[j].x, b[j].y);
        }
    };

    load_stage(0, 0); cpcommit();
    load_stage(1, 1); cpcommit();
    load_stage(2, 2); cpcommit();

    for (int ci = 0; ci < NTI; ci += 2) {
        if (ci + 3 < NTI) load_stage(ci + 3, (ci + 3) % 6);
        cpcommit();
        cpwait<2>();
        __syncthreads();
        compute(ci);
        if (ci + 4 < NTI) load_stage(ci + 4, (ci + 4) % 6);
        cpcommit();
        compute(ci + 1);
    }

    // epilogue: + bias -> y
    const int nb = bn * 128 + wn * 64;
    #pragma unroll
    for (int i = 0; i < 4; i++) {
        #pragma unroll
        for (int h = 0; h < 2; h++) {
            const int m = bm * 128 + wm * 64 + i * 16 + h * 8 + (lane >> 2);
            float* crow = C + (size_t)m * DOUT + nb + (lane & 3) * 2;
            #pragma unroll
            for (int j = 0; j < 8; j++) {
                const float2 bv = *reinterpret_cast<const float2*>(
                    bias + nb + j * 8 + (lane & 3) * 2);
                float2 v;
                v.x = acc[i][j][h * 2 + 0] + bv.x;
                v.y = acc[i][j][h * 2 + 1] + bv.y;
                *reinterpret_cast<float2*>(crow + j * 8) = v;
            }
        }
    }
}

// ---------------------------------------------------------------------------
extern "C" void kernel_launch(void* const* d_in, const int* in_sizes, int n_in,
                              void* d_out, int out_size)
{
    const float* x    = (const float*)d_in[0];
    const int*   t2s  = (const int*)  d_in[1];
    const float* w    = (const float*)d_in[2];
    const float* bias = (const float*)d_in[3];
    const float* lA   = (const float*)d_in[4];
    const float* lB   = (const float*)d_in[5];
    const float* scal = (const float*)d_in[6];
    float*       y    = (float*)d_out;

    constexpr int SMEM0 = 4 * (1024 + 2048) * 4;  // 48 KB (lora)
    constexpr int SMEM1 = 6 * (2048 + 2048) * 4;  // 96 KB (main)

    cudaFuncSetAttribute(gemm_lora, cudaFuncAttributeMaxDynamicSharedMemorySize, SMEM0);
    cudaFuncSetAttribute(gemm_main, cudaFuncAttributeMaxDynamicSharedMemorySize, SMEM1);

    // 1) convert all operands to fp16 fragment-major scratch
    conv_kernel<<<1184, 256>>>(x, w, lA, lB);
    // 2) lora GEMM: u = mask*scal*(x @ lora_A^T)
    gemm_lora<<<dim3(1, TOK / 64), 128, SMEM0>>>(t2s, scal);
    // 3) main GEMM: y = x@W^T + u@Bcat^T + bias
    gemm_main<<<dim3(DOUT / 128, TOK / 128), 128, SMEM1>>>(y, bias);
}

// round 11
// speedup vs baseline: 3.3125x; 1.0228x over previous
#include <cuda_runtime.h>
#include <cuda_fp16.h>
#include <cstdint>

// ---------------------------------------------------------------------------
// LoRARowParallelLinear, mma.sync fp16 m16n8k16 (compute_103-safe).
//   conv  (R6): x -> fp16 A-frags, W/lora_A -> fp16 B-frags, Bcat.  (~50us)
//   lora  (R6): u = mask*scal*(x @ lora_A^T) -> g_uh fp16 A-frags.  (~20us)
//   main:       y = x@W^T (K=4096) + u@Bcat^T (K-ext) + bias.
//               CTA 128x128, 4 warps (64x64 warp tile), 6 stages, occ 2,
//               barrier every 3 iterations, .cg (L2-only) staging.
// ---------------------------------------------------------------------------

#define DEVINL static __device__ __forceinline__

namespace {
constexpr int TOK = 8192, DIN = 4096, DOUT = 4096;
constexpr int KB16 = DIN / 16;   // 256 k16-blocks
constexpr int NTI  = 132;        // 128 main BK32 iters + 4 K-ext iters (= 44*3)
}

// scratch (allocation-free __device__ globals)
__device__ __align__(128) uint32_t g_xh  [(TOK / 16) * KB16 * 128];  // 67 MB
__device__ __align__(128) uint32_t g_wh  [(DOUT / 8) * KB16 * 64];   // 33.5 MB
__device__ __align__(128) uint32_t g_lah [16 * KB16 * 64];           // 1 MB
__device__ __align__(128) uint32_t g_bcat[(DOUT / 8) * 8 * 64];      // 1 MB
__device__ __align__(128) uint32_t g_uh  [(TOK / 16) * 8 * 128];     // 2 MB

DEVINL uint32_t h2pack(float lo, float hi) {
    __half2 h = __float22half2_rn(make_float2(lo, hi));
    return *reinterpret_cast<uint32_t*>(&h);
}

DEVINL void mma_f16(float& d0, float& d1, float& d2, float& d3,
                    uint32_t a0, uint32_t a1, uint32_t a2, uint32_t a3,
                    uint32_t b0, uint32_t b1)
{
    asm volatile(
        "mma.sync.aligned.m16n8k16.row.col.f32.f16.f16.f32 "
        "{%0,%1,%2,%3},{%4,%5,%6,%7},{%8,%9},{%0,%1,%2,%3};"
        : "+f"(d0), "+f"(d1), "+f"(d2), "+f"(d3)
        : "r"(a0), "r"(a1), "r"(a2), "r"(a3), "r"(b0), "r"(b1));
}

DEVINL void cpa16(const uint32_t* smem_dst, const void* gsrc) {
    uint32_t s = (uint32_t)__cvta_generic_to_shared(smem_dst);
    asm volatile("cp.async.cg.shared.global [%0], [%1], 16;" :: "r"(s), "l"(gsrc));
}
DEVINL void cpcommit() { asm volatile("cp.async.commit_group;"); }
template <int N> DEVINL void cpwait() { asm volatile("cp.async.wait_group %0;" :: "n"(N)); }

// ---------------------------------------------------------------------------
// conv (R6): fp32 -> packed fp16 frag-major, staged through smem.
// ---------------------------------------------------------------------------
__global__ void __launch_bounds__(256) conv_kernel(
    const float* __restrict__ x, const float* __restrict__ w,
    const float* __restrict__ la, const float* __restrict__ lb)
{
    __shared__ float st[8][16 * 36];
    const int tid  = threadIdx.x;
    const int lane = tid & 31, warp = tid >> 5;
    const int gwarp = blockIdx.x * 8 + warp;
    const int nwarp = gridDim.x * 8;
    float* s = st[warp];
    const int g  = lane >> 2;
    const int k0 = (lane & 3) * 2;

    // x -> g_xh (A-frag). Superblock = 16 rows x 32 cols (2 k-blocks).
    {
        const int r = lane >> 1, coff = (lane & 1) * 16;
        for (int sb = gwarp; sb < 512 * 128; sb += nwarp) {
            const int mt = sb >> 7, kt2 = sb & 127;
            const float* base = x + (size_t)(mt * 16) * DIN + kt2 * 32;
            #pragma unroll
            for (int q = 0; q < 4; q++)
                *reinterpret_cast<float4*>(s + r * 36 + coff + q * 4) =
                    *reinterpret_cast<const float4*>(base + (size_t)r * DIN + coff + q * 4);
            __syncwarp();
            #pragma unroll
            for (int kb = 0; kb < 2; kb++) {
                const int K = kb * 16;
                uint4 v;
                v.x = h2pack(s[g * 36 + K + k0],           s[g * 36 + K + k0 + 1]);
                v.y = h2pack(s[(g + 8) * 36 + K + k0],     s[(g + 8) * 36 + K + k0 + 1]);
                v.z = h2pack(s[g * 36 + K + k0 + 8],       s[g * 36 + K + k0 + 9]);
                v.w = h2pack(s[(g + 8) * 36 + K + k0 + 8], s[(g + 8) * 36 + K + k0 + 9]);
                *reinterpret_cast<uint4*>(
                    g_xh + ((size_t)mt * KB16 + kt2 * 2 + kb) * 128 + lane * 4) = v;
            }
            __syncwarp();
        }
    }

    // w -> g_wh (B-frag). Superblock = 8 rows x 32 cols (2 k-blocks).
    {
        const int r = lane >> 2, coff = (lane & 3) * 8;
        for (int sb = gwarp; sb < 512 * 128; sb += nwarp) {
            const int nt = sb >> 7, kt2 = sb & 127;
            const float* base = w + (size_t)(nt * 8) * DIN + kt2 * 32;
            #pragma unroll
            for (int q = 0; q < 2; q++)
                *reinterpret_cast<float4*>(s + r * 36 + coff + q * 4) =
                    *reinterpret_cast<const float4*>(base + (size_t)r * DIN + coff + q * 4);
            __syncwarp();
            #pragma unroll
            for (int kb = 0; kb < 2; kb++) {
                const int K = kb * 16;
                uint2 v;
                v.x = h2pack(s[g * 36 + K + k0],     s[g * 36 + K + k0 + 1]);
                v.y = h2pack(s[g * 36 + K + k0 + 8], s[g * 36 + K + k0 + 9]);
                *reinterpret_cast<uint2*>(
                    g_wh + ((size_t)nt * KB16 + kt2 * 2 + kb) * 64 + lane * 2) = v;
            }
            __syncwarp();
        }
    }

    // lora_A -> g_lah (B-frag, 16 n-tiles)
    {
        const int r = lane >> 2, coff = (lane & 3) * 8;
        for (int sb = gwarp; sb < 16 * 128; sb += nwarp) {
            const int nt = sb >> 7, kt2 = sb & 127;
            const float* base = la + (size_t)(nt * 8) * DIN + kt2 * 32;
            #pragma unroll
            for (int q = 0; q < 2; q++)
                *reinterpret_cast<float4*>(s + r * 36 + coff + q * 4) =
                    *reinterpret_cast<const float4*>(base + (size_t)r * DIN + coff + q * 4);
            __syncwarp();
            #pragma unroll
            for (int kb = 0; kb < 2; kb++) {
                const int K = kb * 16;
                uint2 v;
                v.x = h2pack(s[g * 36 + K + k0],     s[g * 36 + K + k0 + 1]);
                v.y = h2pack(s[g * 36 + K + k0 + 8], s[g * 36 + K + k0 + 9]);
                *reinterpret_cast<uint2*>(
                    g_lah + ((size_t)nt * KB16 + kt2 * 2 + kb) * 64 + lane * 2) = v;
            }
            __syncwarp();
        }
    }

    // lora_B [8][DOUT][16] -> g_bcat (B-frag): Bcat[n][s*16+r] = lB[s][n][r]
    const int nth = gridDim.x * blockDim.x;
    const int gt  = blockIdx.x * 256 + tid;
    for (int i = gt; i < DOUT * 64; i += nth) {
        const int n = i >> 6, p = i & 63;
        const int kc = p * 2;
        const int sl = kc >> 4, rr = kc & 15;
        const float f0 = lb[(size_t)sl * DOUT * 16 + n * 16 + rr];
        const float f1 = lb[(size_t)sl * DOUT * 16 + n * 16 + rr + 1];
        const int nt = n >> 3, gg = n & 7;
        const int kbb  = kc >> 4;
        const int lpos = gg * 4 + ((kc & 7) >> 1);
        const int word = lpos * 2 + ((kc >> 3) & 1);
        g_bcat[((size_t)nt * 8 + kbb) * 64 + word] = h2pack(f0, f1);
    }
}

// ---------------------------------------------------------------------------
// lora (R6): u = mask*scal*(x @ lora_A^T) -> g_uh (fp16 A-frag).
// CTA 64x128, 128 thr (4 warps, warp 32x64), BK=32, 4 stages, 48KB.
// ---------------------------------------------------------------------------
__global__ void __launch_bounds__(128, 3) gemm_lora(
    const int* __restrict__ t2s, const float* __restrict__ scal)
{
    constexpr int A_ST = 1024, B_ST = 2048, STW = A_ST + B_ST;  // words
    extern __shared__ uint32_t sm[];
    const int tid = threadIdx.x, lane = tid & 31, warp = tid >> 5;
    const int wm = warp >> 1, wn = warp & 1;
    const int bm = blockIdx.y;

    float acc[2][8][4];
    #pragma unroll
    for (int i = 0; i < 2; i++)
        #pragma unroll
        for (int j = 0; j < 8; j++)
            #pragma unroll
            for (int k = 0; k < 4; k++) acc[i][j][k] = 0.f;

    auto load_stage = [&](int f, int buf) {
        uint32_t* sA = sm + buf * STW;
        uint32_t* sB = sA + A_ST;
        #pragma unroll
        for (int q = tid; q < 256; q += 128) {
            const int mt = q >> 6, kb = (q >> 5) & 1, c = q & 31;
            cpa16(sA + (mt * 2 + kb) * 128 + c * 4,
                  g_xh + ((size_t)(bm * 4 + mt) * KB16 + f * 2 + kb) * 128 + c * 4);
        }
        #pragma unroll
        for (int q = tid; q < 512; q += 128) {
            const int nt = q >> 5, kb = (q >> 4) & 1, c = q & 15;
            cpa16(sB + (nt * 2 + kb) * 64 + c * 4,
                  g_lah + ((size_t)nt * KB16 + f * 2 + kb) * 64 + c * 4);
        }
    };

    load_stage(0, 0); cpcommit();
    load_stage(1, 1); cpcommit();
    load_stage(2, 2); cpcommit();

    for (int ci = 0; ci < 128; ci++) {
        cpwait<2>();
        __syncthreads();
        if (ci + 3 < 128) load_stage(ci + 3, (ci + 3) & 3);
        cpcommit();

        const uint32_t* sA = sm + (ci & 3) * STW;
        const uint32_t* sB = sA + A_ST;
        const uint32_t* aw = sA + (wm * 2) * 2 * 128 + lane * 4;
        const uint32_t* bw = sB + (wn * 8) * 2 * 64 + lane * 2;

        #pragma unroll
        for (int kb = 0; kb < 2; kb++) {
            uint4 a[2];
            a[0] = *reinterpret_cast<const uint4*>(aw + kb * 128);
            a[1] = *reinterpret_cast<const uint4*>(aw + (2 + kb) * 128);
            uint2 b[8];
            #pragma unroll
            for (int j = 0; j < 8; j++)
                b[j] = *reinterpret_cast<const uint2*>(bw + (j * 2 + kb) * 64);
            #pragma unroll
            for (int i = 0; i < 2; i++)
                #pragma unroll
                for (int j = 0; j < 8; j++)
                    mma_f16(acc[i][j][0], acc[i][j][1], acc[i][j][2], acc[i][j][3],
                            a[i].x, a[i].y, a[i].z, a[i].w, b[j].x, b[j].y);
        }
    }

    // epilogue: mask*scale -> g_uh fp16 A-frag blocks
    #pragma unroll
    for (int i = 0; i < 2; i++) {
        const int mrow0 = bm * 64 + wm * 32 + i * 16 + (lane >> 2);
        const int slot0 = t2s[mrow0];
        const int slot1 = t2s[mrow0 + 8];
        const float sc0 = scal[slot0];
        const float sc1 = scal[slot1];
        const int mt = bm * 4 + wm * 2 + i;
        #pragma unroll
        for (int j = 0; j < 8; j += 2) {
            const int kbg = wn * 4 + (j >> 1);
            const int n0 = wn * 64 + j * 8 + (lane & 3) * 2;
            const int n1 = n0 + 8;
            const float m00 = ((n0 >> 4) == slot0) ? sc0 : 0.f;
            const float m01 = ((n0 >> 4) == slot1) ? sc1 : 0.f;
            const float m10 = ((n1 >> 4) == slot0) ? sc0 : 0.f;
            const float m11 = ((n1 >> 4) == slot1) ? sc1 : 0.f;
            uint4 v;
            v.x = h2pack(acc[i][j][0] * m00,     acc[i][j][1] * m00);
            v.y = h2pack(acc[i][j][2] * m01,     acc[i][j][3] * m01);
            v.z = h2pack(acc[i][j + 1][0] * m10, acc[i][j + 1][1] * m10);
            v.w = h2pack(acc[i][j + 1][2] * m11, acc[i][j + 1][3] * m11);
            *reinterpret_cast<uint4*>(g_uh + ((size_t)mt * 8 + kbg) * 128 + lane * 4) = v;
        }
    }
}

// ---------------------------------------------------------------------------
// main: CTA 128x128, 128 thr (4 warps, warp 64x64), BK=32, 6 stages, occ 2,
// barrier every 3 iterations, per-subiteration cpwait for correctness.
// ---------------------------------------------------------------------------
__global__ void __launch_bounds__(128, 2) gemm_main(
    float* __restrict__ C, const float* __restrict__ bias)
{
    constexpr int A_ST = 2048, B_ST = 2048, STW = A_ST + B_ST;  // words/stage
    extern __shared__ uint32_t sm[];
    const int tid = threadIdx.x, lane = tid & 31, warp = tid >> 5;
    const int wm = warp >> 1, wn = warp & 1;
    const int bm = blockIdx.y, bn = blockIdx.x;

    float acc[4][8][4];
    #pragma unroll
    for (int i = 0; i < 4; i++)
        #pragma unroll
        for (int j = 0; j < 8; j++)
            #pragma unroll
            for (int k = 0; k < 4; k++) acc[i][j][k] = 0.f;

    auto load_stage = [&](int f, int buf) {
        uint32_t* sA = sm + buf * STW;
        uint32_t* sB = sA + A_ST;
        #pragma unroll
        for (int q = tid; q < 512; q += 128) {
            const int mt = q >> 6, kb = (q >> 5) & 1, c = q & 31;
            const uint32_t* src = (f < 128)
                ? g_xh + ((size_t)(bm * 8 + mt) * KB16 + f * 2 + kb) * 128 + c * 4
                : g_uh + ((size_t)(bm * 8 + mt) * 8 + (f - 128) * 2 + kb) * 128 + c * 4;
            cpa16(sA + (mt * 2 + kb) * 128 + c * 4, src);
        }
        #pragma unroll
        for (int q = tid; q < 512; q += 128) {
            const int nt = q >> 5, kb = (q >> 4) & 1, c = q & 15;
            const uint32_t* src = (f < 128)
                ? g_wh   + ((size_t)(bn * 16 + nt) * KB16 + f * 2 + kb) * 64 + c * 4
                : g_bcat + ((size_t)(bn * 16 + nt) * 8 + (f - 128) * 2 + kb) * 64 + c * 4;
            cpa16(sB + (nt * 2 + kb) * 64 + c * 4, src);
        }
    };

    auto compute = [&](int ci) {
        const uint32_t* sA = sm + (ci % 6) * STW;
        const uint32_t* sB = sA + A_ST;
        const uint32_t* aw = sA + (wm * 4) * 2 * 128 + lane * 4;
        const uint32_t* bw = sB + (wn * 8) * 2 * 64 + lane * 2;
        #pragma unroll
        for (int kb = 0; kb < 2; kb++) {
            uint4 a[4];
            #pragma unroll
            for (int i = 0; i < 4; i++)
                a[i] = *reinterpret_cast<const uint4*>(aw + (i * 2 + kb) * 128);
            uint2 b[8];
            #pragma unroll
            for (int j = 0; j < 8; j++)
                b[j] = *reinterpret_cast<const uint2*>(bw + (j * 2 + kb) * 64);
            #pragma unroll
            for (int i = 0; i < 4; i++)
                #pragma unroll
                for (int j = 0; j < 8; j++)
                    mma_f16(acc[i][j][0], acc[i][j][1], acc[i][j][2], acc[i][j][3],
                            a[i].x, a[i].y, a[i].z, a[i].w, b[j].x, b[j].y);
        }
    };

    load_stage(0, 0); cpcommit();
    load_stage(1, 1); cpcommit();
    load_stage(2, 2); cpcommit();

    // Window of 3 iterations, one CTA barrier per window (44 barriers).
    // All fills occur after the window barrier; targets (ci+3..ci+5)%6 are
    // disjoint from this window's read set {ci..ci+2}%6. Each cpwait<2>
    // guarantees the stage about to be read is complete before use.
    for (int ci = 0; ci < NTI; ci += 3) {
        cpwait<2>();
        __syncthreads();
        if (ci + 3 < NTI) load_stage(ci + 3, (ci + 3) % 6);
        cpcommit();
        compute(ci);
        cpwait<2>();
        if (ci + 4 < NTI) load_stage(ci + 4, (ci + 4) % 6);
        cpcommit();
        compute(ci + 1);
        cpwait<2>();
        if (ci + 5 < NTI) load_stage(ci + 5, (ci + 5) % 6);
        cpcommit();
        compute(ci + 2);
    }

    // epilogue: + bias -> y
    const int nb = bn * 128 + wn * 64;
    #pragma unroll
    for (int i = 0; i < 4; i++) {
        #pragma unroll
        for (int h = 0; h < 2; h++) {
            const int m = bm * 128 + wm * 64 + i * 16 + h * 8 + (lane >> 2);
            float* crow = C + (size_t)m * DOUT + nb + (lane & 3) * 2;
            #pragma unroll
            for (int j = 0; j < 8; j++) {
                const float2 bv = *reinterpret_cast<const float2*>(
                    bias + nb + j * 8 + (lane & 3) * 2);
                float2 v;
                v.x = acc[i][j][h * 2 + 0] + bv.x;
                v.y = acc[i][j][h * 2 + 1] + bv.y;
                *reinterpret_cast<float2*>(crow + j * 8) = v;
            }
        }
    }
}

// ---------------------------------------------------------------------------
extern "C" void kernel_launch(void* const* d_in, const int* in_sizes, int n_in,
                              void* d_out, int out_size)
{
    const float* x    = (const float*)d_in[0];
    const int*   t2s  = (const int*)  d_in[1];
    const float* w    = (const float*)d_in[2];
    const float* bias = (const float*)d_in[3];
    const float* lA   = (const float*)d_in[4];
    const float* lB   = (const float*)d_in[5];
    const float* scal = (const float*)d_in[6];
    float*       y    = (float*)d_out;

    constexpr int SMEM0 = 4 * (1024 + 2048) * 4;  // 48 KB (lora)
    constexpr int SMEM1 = 6 * (2048 + 2048) * 4;  // 96 KB (main)

    cudaFuncSetAttribute(gemm_lora, cudaFuncAttributeMaxDynamicSharedMemorySize, SMEM0);
    cudaFuncSetAttribute(gemm_main, cudaFuncAttributeMaxDynamicSharedMemorySize, SMEM1);

    // 1) convert all operands to fp16 fragment-major scratch
    conv_kernel<<<1184, 256>>>(x, w, lA, lB);
    // 2) lora GEMM: u = mask*scal*(x @ lora_A^T)
    gemm_lora<<<dim3(1, TOK / 64), 128, SMEM0>>>(t2s, scal);
    // 3) main GEMM: y = x@W^T + u@Bcat^T + bias
    gemm_main<<<dim3(DOUT / 128, TOK / 128), 128, SMEM1>>>(y, bias);
}

// round 12
// speedup vs baseline: 3.5965x; 1.0857x over previous
#include <cuda_runtime.h>
#include <cuda_fp16.h>
#include <cstdint>

// ---------------------------------------------------------------------------
// LoRARowParallelLinear, mma.sync fp16 m16n8k16 (compute_103-safe).
//   conv:  x -> fp16 A-frags, W/lora_A -> fp16 B-frags, Bcat; zeroes g_flag.
//   fused: blocks [0,128)   = lora GEMM u = mask*scal*(x @ lora_A^T) -> g_uh,
//                             then release g_flag.
//          blocks [128,2176)= main GEMM y = x@W^T + u@Bcat^T (K-ext) + bias;
//                             acquire-spin on g_flag just before the K-ext
//                             window (ci=123), ~93% into the mainloop.
//   main config: CTA 128x128, 4 warps (64x64 warp tile), 6 stages, occ 2,
//   barrier every 3 iterations, .cg (L2-only) staging.
// ---------------------------------------------------------------------------

#define DEVINL static __device__ __forceinline__

namespace {
constexpr int TOK = 8192, DIN = 4096, DOUT = 4096;
constexpr int KB16 = DIN / 16;   // 256 k16-blocks
constexpr int NTI  = 132;        // 128 main BK32 iters + 4 K-ext iters (= 44*3)
}

// scratch (allocation-free __device__ globals)
__device__ __align__(128) uint32_t g_xh  [(TOK / 16) * KB16 * 128];  // 67 MB
__device__ __align__(128) uint32_t g_wh  [(DOUT / 8) * KB16 * 64];   // 33.5 MB
__device__ __align__(128) uint32_t g_lah [16 * KB16 * 64];           // 1 MB
__device__ __align__(128) uint32_t g_bcat[(DOUT / 8) * 8 * 64];      // 1 MB
__device__ __align__(128) uint32_t g_uh  [(TOK / 16) * 8 * 128];     // 2 MB
__device__ int g_flag;

DEVINL uint32_t h2pack(float lo, float hi) {
    __half2 h = __float22half2_rn(make_float2(lo, hi));
    return *reinterpret_cast<uint32_t*>(&h);
}

DEVINL void mma_f16(float& d0, float& d1, float& d2, float& d3,
                    uint32_t a0, uint32_t a1, uint32_t a2, uint32_t a3,
                    uint32_t b0, uint32_t b1)
{
    asm volatile(
        "mma.sync.aligned.m16n8k16.row.col.f32.f16.f16.f32 "
        "{%0,%1,%2,%3},{%4,%5,%6,%7},{%8,%9},{%0,%1,%2,%3};"
        : "+f"(d0), "+f"(d1), "+f"(d2), "+f"(d3)
        : "r"(a0), "r"(a1), "r"(a2), "r"(a3), "r"(b0), "r"(b1));
}

DEVINL void cpa16(const uint32_t* smem_dst, const void* gsrc) {
    uint32_t s = (uint32_t)__cvta_generic_to_shared(smem_dst);
    asm volatile("cp.async.cg.shared.global [%0], [%1], 16;" :: "r"(s), "l"(gsrc));
}
DEVINL void cpcommit() { asm volatile("cp.async.commit_group;"); }
template <int N> DEVINL void cpwait() { asm volatile("cp.async.wait_group %0;" :: "n"(N)); }

// ---------------------------------------------------------------------------
// conv: fp32 -> packed fp16 frag-major, staged through smem. Zeroes g_flag.
// ---------------------------------------------------------------------------
__global__ void __launch_bounds__(256) conv_kernel(
    const float* __restrict__ x, const float* __restrict__ w,
    const float* __restrict__ la, const float* __restrict__ lb)
{
    if (blockIdx.x == 0 && threadIdx.x == 0) g_flag = 0;

    __shared__ float st[8][16 * 36];
    const int tid  = threadIdx.x;
    const int lane = tid & 31, warp = tid >> 5;
    const int gwarp = blockIdx.x * 8 + warp;
    const int nwarp = gridDim.x * 8;
    float* s = st[warp];
    const int g  = lane >> 2;
    const int k0 = (lane & 3) * 2;

    // x -> g_xh (A-frag). Superblock = 16 rows x 32 cols (2 k-blocks).
    {
        const int r = lane >> 1, coff = (lane & 1) * 16;
        for (int sb = gwarp; sb < 512 * 128; sb += nwarp) {
            const int mt = sb >> 7, kt2 = sb & 127;
            const float* base = x + (size_t)(mt * 16) * DIN + kt2 * 32;
            #pragma unroll
            for (int q = 0; q < 4; q++)
                *reinterpret_cast<float4*>(s + r * 36 + coff + q * 4) =
                    *reinterpret_cast<const float4*>(base + (size_t)r * DIN + coff + q * 4);
            __syncwarp();
            #pragma unroll
            for (int kb = 0; kb < 2; kb++) {
                const int K = kb * 16;
                uint4 v;
                v.x = h2pack(s[g * 36 + K + k0],           s[g * 36 + K + k0 + 1]);
                v.y = h2pack(s[(g + 8) * 36 + K + k0],     s[(g + 8) * 36 + K + k0 + 1]);
                v.z = h2pack(s[g * 36 + K + k0 + 8],       s[g * 36 + K + k0 + 9]);
                v.w = h2pack(s[(g + 8) * 36 + K + k0 + 8], s[(g + 8) * 36 + K + k0 + 9]);
                *reinterpret_cast<uint4*>(
                    g_xh + ((size_t)mt * KB16 + kt2 * 2 + kb) * 128 + lane * 4) = v;
            }
            __syncwarp();
        }
    }

    // w -> g_wh (B-frag). Superblock = 8 rows x 32 cols (2 k-blocks).
    {
        const int r = lane >> 2, coff = (lane & 3) * 8;
        for (int sb = gwarp; sb < 512 * 128; sb += nwarp) {
            const int nt = sb >> 7, kt2 = sb & 127;
            const float* base = w + (size_t)(nt * 8) * DIN + kt2 * 32;
            #pragma unroll
            for (int q = 0; q < 2; q++)
                *reinterpret_cast<float4*>(s + r * 36 + coff + q * 4) =
                    *reinterpret_cast<const float4*>(base + (size_t)r * DIN + coff + q * 4);
            __syncwarp();
            #pragma unroll
            for (int kb = 0; kb < 2; kb++) {
                const int K = kb * 16;
                uint2 v;
                v.x = h2pack(s[g * 36 + K + k0],     s[g * 36 + K + k0 + 1]);
                v.y = h2pack(s[g * 36 + K + k0 + 8], s[g * 36 + K + k0 + 9]);
                *reinterpret_cast<uint2*>(
                    g_wh + ((size_t)nt * KB16 + kt2 * 2 + kb) * 64 + lane * 2) = v;
            }
            __syncwarp();
        }
    }

    // lora_A -> g_lah (B-frag, 16 n-tiles)
    {
        const int r = lane >> 2, coff = (lane & 3) * 8;
        for (int sb = gwarp; sb < 16 * 128; sb += nwarp) {
            const int nt = sb >> 7, kt2 = sb & 127;
            const float* base = la + (size_t)(nt * 8) * DIN + kt2 * 32;
            #pragma unroll
            for (int q = 0; q < 2; q++)
                *reinterpret_cast<float4*>(s + r * 36 + coff + q * 4) =
                    *reinterpret_cast<const float4*>(base + (size_t)r * DIN + coff + q * 4);
            __syncwarp();
            #pragma unroll
            for (int kb = 0; kb < 2; kb++) {
                const int K = kb * 16;
                uint2 v;
                v.x = h2pack(s[g * 36 + K + k0],     s[g * 36 + K + k0 + 1]);
                v.y = h2pack(s[g * 36 + K + k0 + 8], s[g * 36 + K + k0 + 9]);
                *reinterpret_cast<uint2*>(
                    g_lah + ((size_t)nt * KB16 + kt2 * 2 + kb) * 64 + lane * 2) = v;
            }
            __syncwarp();
        }
    }

    // lora_B [8][DOUT][16] -> g_bcat (B-frag): Bcat[n][s*16+r] = lB[s][n][r]
    const int nth = gridDim.x * blockDim.x;
    const int gt  = blockIdx.x * 256 + tid;
    for (int i = gt; i < DOUT * 64; i += nth) {
        const int n = i >> 6, p = i & 63;
        const int kc = p * 2;
        const int sl = kc >> 4, rr = kc & 15;
        const float f0 = lb[(size_t)sl * DOUT * 16 + n * 16 + rr];
        const float f1 = lb[(size_t)sl * DOUT * 16 + n * 16 + rr + 1];
        const int nt = n >> 3, gg = n & 7;
        const int kbb  = kc >> 4;
        const int lpos = gg * 4 + ((kc & 7) >> 1);
        const int word = lpos * 2 + ((kc >> 3) & 1);
        g_bcat[((size_t)nt * 8 + kbb) * 64 + word] = h2pack(f0, f1);
    }
}

// ---------------------------------------------------------------------------
// fused kernel: lora blocks [0,128) + main blocks [128,2176).
// ---------------------------------------------------------------------------
__global__ void __launch_bounds__(128, 2) gemm_fused(
    float* __restrict__ C, const float* __restrict__ bias,
    const int* __restrict__ t2s, const float* __restrict__ scal)
{
    extern __shared__ uint32_t sm[];
    const int tid = threadIdx.x, lane = tid & 31, warp = tid >> 5;
    const int wm = warp >> 1, wn = warp & 1;

    if (blockIdx.x < 128) {
        // -------- lora GEMM (R6-proven): u = mask*scal*(x @ lora_A^T) --------
        constexpr int A_ST = 1024, B_ST = 2048, STW = A_ST + B_ST;  // words
        const int bm = blockIdx.x;

        float acc[2][8][4];
        #pragma unroll
        for (int i = 0; i < 2; i++)
            #pragma unroll
            for (int j = 0; j < 8; j++)
                #pragma unroll
                for (int k = 0; k < 4; k++) acc[i][j][k] = 0.f;

        auto load_stage = [&](int f, int buf) {
            uint32_t* sA = sm + buf * STW;
            uint32_t* sB = sA + A_ST;
            #pragma unroll
            for (int q = tid; q < 256; q += 128) {
                const int mt = q >> 6, kb = (q >> 5) & 1, c = q & 31;
                cpa16(sA + (mt * 2 + kb) * 128 + c * 4,
                      g_xh + ((size_t)(bm * 4 + mt) * KB16 + f * 2 + kb) * 128 + c * 4);
            }
            #pragma unroll
            for (int q = tid; q < 512; q += 128) {
                const int nt = q >> 5, kb = (q >> 4) & 1, c = q & 15;
                cpa16(sB + (nt * 2 + kb) * 64 + c * 4,
                      g_lah + ((size_t)nt * KB16 + f * 2 + kb) * 64 + c * 4);
            }
        };

        load_stage(0, 0); cpcommit();
        load_stage(1, 1); cpcommit();
        load_stage(2, 2); cpcommit();

        for (int ci = 0; ci < 128; ci++) {
            cpwait<2>();
            __syncthreads();
            if (ci + 3 < 128) load_stage(ci + 3, (ci + 3) & 3);
            cpcommit();

            const uint32_t* sA = sm + (ci & 3) * STW;
            const uint32_t* sB = sA + A_ST;
            const uint32_t* aw = sA + (wm * 2) * 2 * 128 + lane * 4;
            const uint32_t* bw = sB + (wn * 8) * 2 * 64 + lane * 2;

            #pragma unroll
            for (int kb = 0; kb < 2; kb++) {
                uint4 a[2];
                a[0] = *reinterpret_cast<const uint4*>(aw + kb * 128);
                a[1] = *reinterpret_cast<const uint4*>(aw + (2 + kb) * 128);
                uint2 b[8];
                #pragma unroll
                for (int j = 0; j < 8; j++)
                    b[j] = *reinterpret_cast<const uint2*>(bw + (j * 2 + kb) * 64);
                #pragma unroll
                for (int i = 0; i < 2; i++)
                    #pragma unroll
                    for (int j = 0; j < 8; j++)
                        mma_f16(acc[i][j][0], acc[i][j][1], acc[i][j][2], acc[i][j][3],
                                a[i].x, a[i].y, a[i].z, a[i].w, b[j].x, b[j].y);
            }
        }

        // epilogue: mask*scale -> g_uh fp16 A-frag blocks
        #pragma unroll
        for (int i = 0; i < 2; i++) {
            const int mrow0 = bm * 64 + wm * 32 + i * 16 + (lane >> 2);
            const int slot0 = t2s[mrow0];
            const int slot1 = t2s[mrow0 + 8];
            const float sc0 = scal[slot0];
            const float sc1 = scal[slot1];
            const int mt = bm * 4 + wm * 2 + i;
            #pragma unroll
            for (int j = 0; j < 8; j += 2) {
                const int kbg = wn * 4 + (j >> 1);
                const int n0 = wn * 64 + j * 8 + (lane & 3) * 2;
                const int n1 = n0 + 8;
                const float m00 = ((n0 >> 4) == slot0) ? sc0 : 0.f;
                const float m01 = ((n0 >> 4) == slot1) ? sc1 : 0.f;
                const float m10 = ((n1 >> 4) == slot0) ? sc0 : 0.f;
                const float m11 = ((n1 >> 4) == slot1) ? sc1 : 0.f;
                uint4 v;
                v.x = h2pack(acc[i][j][0] * m00,     acc[i][j][1] * m00);
                v.y = h2pack(acc[i][j][2] * m01,     acc[i][j][3] * m01);
                v.z = h2pack(acc[i][j + 1][0] * m10, acc[i][j + 1][1] * m10);
                v.w = h2pack(acc[i][j + 1][2] * m11, acc[i][j + 1][3] * m11);
                *reinterpret_cast<uint4*>(g_uh + ((size_t)mt * 8 + kbg) * 128 + lane * 4) = v;
            }
        }

        // release: u slice visible, count this block done
        __threadfence();
        __syncthreads();
        if (tid == 0) atomicAdd(&g_flag, 1);
        return;
    }

    // -------- main GEMM --------
    constexpr int A_ST = 2048, B_ST = 2048, STW = A_ST + B_ST;  // words/stage
    const int mid = blockIdx.x - 128;
    const int bn = mid & 31, bm = mid >> 5;

    float acc[4][8][4];
    #pragma unroll
    for (int i = 0; i < 4; i++)
        #pragma unroll
        for (int j = 0; j < 8; j++)
            #pragma unroll
            for (int k = 0; k < 4; k++) acc[i][j][k] = 0.f;

    auto load_stage = [&](int f, int buf) {
        uint32_t* sA = sm + buf * STW;
        uint32_t* sB = sA + A_ST;
        #pragma unroll
        for (int q = tid; q < 512; q += 128) {
            const int mt = q >> 6, kb = (q >> 5) & 1, c = q & 31;
            const uint32_t* src = (f < 128)
                ? g_xh + ((size_t)(bm * 8 + mt) * KB16 + f * 2 + kb) * 128 + c * 4
                : g_uh + ((size_t)(bm * 8 + mt) * 8 + (f - 128) * 2 + kb) * 128 + c * 4;
            cpa16(sA + (mt * 2 + kb) * 128 + c * 4, src);
        }
        #pragma unroll
        for (int q = tid; q < 512; q += 128) {
            const int nt = q >> 5, kb = (q >> 4) & 1, c = q & 15;
            const uint32_t* src = (f < 128)
                ? g_wh   + ((size_t)(bn * 16 + nt) * KB16 + f * 2 + kb) * 64 + c * 4
                : g_bcat + ((size_t)(bn * 16 + nt) * 8 + (f - 128) * 2 + kb) * 64 + c * 4;
            cpa16(sB + (nt * 2 + kb) * 64 + c * 4, src);
        }
    };

    auto compute = [&](int ci) {
        const uint32_t* sA = sm + (ci % 6) * STW;
        const uint32_t* sB = sA + A_ST;
        const uint32_t* aw = sA + (wm * 4) * 2 * 128 + lane * 4;
        const uint32_t* bw = sB + (wn * 8) * 2 * 64 + lane * 2;
        #pragma unroll
        for (int kb = 0; kb < 2; kb++) {
            uint4 a[4];
            #pragma unroll
            for (int i = 0; i < 4; i++)
                a[i] = *reinterpret_cast<const uint4*>(aw + (i * 2 + kb) * 128);
            uint2 b[8];
            #pragma unroll
            for (int j = 0; j < 8; j++)
                b[j] = *reinterpret_cast<const uint2*>(bw + (j * 2 + kb) * 64);
            #pragma unroll
            for (int i = 0; i < 4; i++)
                #pragma unroll
                for (int j = 0; j < 8; j++)
                    mma_f16(acc[i][j][0], acc[i][j][1], acc[i][j][2], acc[i][j][3],
                            a[i].x, a[i].y, a[i].z, a[i].w, b[j].x, b[j].y);
        }
    };

    auto window = [&](int ci) {
        cpwait<2>();
        __syncthreads();
        if (ci + 3 < NTI) load_stage(ci + 3, (ci + 3) % 6);
        cpcommit();
        compute(ci);
        cpwait<2>();
        if (ci + 4 < NTI) load_stage(ci + 4, (ci + 4) % 6);
        cpcommit();
        compute(ci + 1);
        cpwait<2>();
        if (ci + 5 < NTI) load_stage(ci + 5, (ci + 5) % 6);
        cpcommit();
        compute(ci + 2);
    };

    load_stage(0, 0); cpcommit();
    load_stage(1, 1); cpcommit();
    load_stage(2, 2); cpcommit();

    // windows 0..120: all fills f <= 125 (< 128), no g_uh dependency
    for (int ci = 0; ci < 123; ci += 3) window(ci);

    // acquire: all 128 lora blocks must have published g_uh before fills
    // of f >= 128 (first issued in window 123).
    if (tid == 0) {
        int v;
        do {
            asm volatile("ld.acquire.gpu.global.b32 %0, [%1];"
                         : "=r"(v) : "l"(&g_flag) : "memory");
        } while (v < 128);
    }
    __syncthreads();

    // windows 123, 126, 129 (fills f = 126..131)
    for (int ci = 123; ci < NTI; ci += 3) window(ci);

    // epilogue: + bias -> y
    const int nb = bn * 128 + wn * 64;
    #pragma unroll
    for (int i = 0; i < 4; i++) {
        #pragma unroll
        for (int h = 0; h < 2; h++) {
            const int m = bm * 128 + wm * 64 + i * 16 + h * 8 + (lane >> 2);
            float* crow = C + (size_t)m * DOUT + nb + (lane & 3) * 2;
            #pragma unroll
            for (int j = 0; j < 8; j++) {
                const float2 bv = *reinterpret_cast<const float2*>(
                    bias + nb + j * 8 + (lane & 3) * 2);
                float2 v;
                v.x = acc[i][j][h * 2 + 0] + bv.x;
                v.y = acc[i][j][h * 2 + 1] + bv.y;
                *reinterpret_cast<float2*>(crow + j * 8) = v;
            }
        }
    }
}

// ---------------------------------------------------------------------------
extern "C" void kernel_launch(void* const* d_in, const int* in_sizes, int n_in,
                              void* d_out, int out_size)
{
    const float* x    = (const float*)d_in[0];
    const int*   t2s  = (const int*)  d_in[1];
    const float* w    = (const float*)d_in[2];
    const float* bias = (const float*)d_in[3];
    const float* lA   = (const float*)d_in[4];
    const float* lB   = (const float*)d_in[5];
    const float* scal = (const float*)d_in[6];
    float*       y    = (float*)d_out;

    constexpr int SMEM1 = 6 * (2048 + 2048) * 4;  // 96 KB (covers lora's 48 KB)

    cudaFuncSetAttribute(gemm_fused, cudaFuncAttributeMaxDynamicSharedMemorySize, SMEM1);

    // 1) convert all operands to fp16 fragment-major scratch; reset flag
    conv_kernel<<<1184, 256>>>(x, w, lA, lB);
    // 2) fused: lora blocks (0..127) + main blocks (128..2175)
    gemm_fused<<<128 + 2048, 128, SMEM1>>>(y, bias, t2s, scal);
}